// round 10
// baseline (speedup 1.0000x reference)
#include <cuda_runtime.h>
#include <cuda_bf16.h>
#include <math.h>
#include <stdint.h>

#define NPTS 100000
#define CH 128
#define CH2 256
#define NPLANES 64
#define FEAT_OUT 140

// ------------------------- scratch (__device__ globals) ----------------------
__device__ __nv_bfloat16 g_Hh [(size_t)NPTS * CH2];   // fc1 out hi
__device__ __nv_bfloat16 g_Hl [(size_t)NPTS * CH2];   // fc1 out lo
__device__ float         g_h2 [(size_t)NPTS * CH];    // fc2 out fp32
__device__ __nv_bfloat16 g_h2h[(size_t)NPTS * CH];    // fc2 out hi
__device__ __nv_bfloat16 g_h2l[(size_t)NPTS * CH];    // fc2 out lo
__device__ float         g_a  [(size_t)NPTS * CH];    // attention activations
__device__ float g_num[2 * NPLANES * CH];
__device__ float g_den[2 * NPLANES * CH];
__device__ unsigned g_cmax[CH];

// pre-split weights, [n][k] layout (bf16 hi/lo)
__device__ __nv_bfloat16 g_W1h[CH2 * CH], g_W1l[CH2 * CH];     // n=256, k=128
__device__ __nv_bfloat16 g_W2h[CH * CH2], g_W2l[CH * CH2];     // n=128, k=256
__device__ __nv_bfloat16 g_Wah[CH * CH],  g_Wal[CH * CH];      // n=128, k=128

__device__ __forceinline__ unsigned encf(float f) {
    unsigned u = __float_as_uint(f);
    return (u & 0x80000000u) ? ~u : (u | 0x80000000u);
}
__device__ __forceinline__ float decf(unsigned u) {
    return __uint_as_float((u & 0x80000000u) ? (u & 0x7fffffffu) : ~u);
}
__device__ __forceinline__ uint32_t pk(__nv_bfloat16 a, __nv_bfloat16 b) {
    return ((uint32_t)__bfloat16_as_ushort(b) << 16) | (uint32_t)__bfloat16_as_ushort(a);
}
__device__ __forceinline__ void bsplit(float f, __nv_bfloat16& h, __nv_bfloat16& l) {
    h = __float2bfloat16(f);
    l = __float2bfloat16(f - __bfloat162float(h));
}

__global__ void init_kernel() {
    int t = blockIdx.x * blockDim.x + threadIdx.x;
    if (t < 2 * NPLANES * CH) { g_num[t] = 0.f; g_den[t] = 0.f; }
    if (t < CH) g_cmax[t] = encf(-3.0e38f);
}

// ---------------- weight pre-split: W[k][n] fp32 -> [n][k] bf16 hi/lo --------
__global__ void prep_kernel(const float* __restrict__ W1, const float* __restrict__ W2,
                            const float* __restrict__ Wa)
{
    int t = blockIdx.x * blockDim.x + threadIdx.x;
    __nv_bfloat16 h, l;
    if (t < 32768) {                       // W1: n 0..255, k 0..127
        int n = t >> 7, k = t & 127;
        bsplit(W1[k * CH2 + n], h, l);
        g_W1h[t] = h; g_W1l[t] = l;
    } else if (t < 65536) {                // W2: n 0..127, k 0..255
        int u = t - 32768;
        int n = u >> 8, k = u & 255;
        bsplit(W2[k * CH + n], h, l);
        g_W2h[u] = h; g_W2l[u] = l;
    } else if (t < 81920) {                // Wa: n 0..127, k 0..127
        int u = t - 65536;
        int n = u >> 7, k = u & 127;
        bsplit(Wa[k * CH + n], h, l);
        g_Wah[u] = h; g_Wal[u] = l;
    }
}

// ------------------------- bf16 HMMA (mma.sync, sm_80+) ----------------------
__device__ __forceinline__ void hmma(float* c, uint32_t a0, uint32_t a1,
                                     uint32_t a2, uint32_t a3,
                                     uint32_t b0, uint32_t b1) {
    asm("mma.sync.aligned.m16n8k16.row.col.f32.bf16.bf16.f32 "
        "{%0,%1,%2,%3},{%4,%5,%6,%7},{%8,%9},{%0,%1,%2,%3};"
        : "+f"(c[0]), "+f"(c[1]), "+f"(c[2]), "+f"(c[3])
        : "r"(a0), "r"(a1), "r"(a2), "r"(a3), "r"(b0), "r"(b1));
}

// ------------------------- SMEM layout ---------------------------------------
#define LDA 136                           // 128 + 8 bf16 pad -> conflict-free frags
#define A_BYTES (128 * LDA * 2)           // 34816
#define OFF_AH  0
#define OFF_AL  A_BYTES
#define OFF_BH  (2 * A_BYTES)
#define OFF_BL  (3 * A_BYTES)
#define OFF_PAR (4 * A_BYTES)             // 139264
#define SMEM_TOT (OFF_PAR + 2048)         // 141312

// ============================================================================
// gemm_mma<KTOT, ASRC, EPI>
//   ASRC 0: A = fp32 gmem (convert+split inline);  1: A = prestored bf16 hi/lo
//   EPI  0: relu(acc*s+b) -> g_Hh/g_Hl (fc1)
//   EPI  1: relu(acc*s+b) -> g_h2 + g_h2h/l, fused fc3 logit -> out   (fc2)
//   EPI  2: raw -> g_a, per-channel colmax -> g_cmax                   (att)
// ============================================================================
template <int KTOT, int ASRC, int EPI>
__global__ __launch_bounds__(256, 1)
void gemm_mma(const float* __restrict__ Af,
              const __nv_bfloat16* __restrict__ Ahg, const __nv_bfloat16* __restrict__ Alg,
              const __nv_bfloat16* __restrict__ Bhg, const __nv_bfloat16* __restrict__ Blg,
              const float* __restrict__ sc, const float* __restrict__ bi,
              const float* __restrict__ W3, const float* __restrict__ b3,
              float* __restrict__ out)
{
    extern __shared__ __align__(16) char smx[];
    __nv_bfloat16* smAh = (__nv_bfloat16*)(smx + OFF_AH);
    __nv_bfloat16* smAl = (__nv_bfloat16*)(smx + OFF_AL);
    __nv_bfloat16* smBh = (__nv_bfloat16*)(smx + OFF_BH);
    __nv_bfloat16* smBl = (__nv_bfloat16*)(smx + OFF_BL);
    float* par = (float*)(smx + OFF_PAR);
    float* psc = par;          float* pbi = par + 128;
    float* pw3 = par + 256;    float* plg = par + 384;
    unsigned* pmax = (unsigned*)(par + 384);

    const int tid = threadIdx.x, wid = tid >> 5, t = tid & 31;
    const int rowBase = blockIdx.x * 128, nBase = blockIdx.y * 128;
    const int warpM = (wid & 3) * 32, warpN = (wid >> 2) * 64;

    if (tid < 128) {
        if (EPI == 0) { psc[tid] = sc[nBase + tid]; pbi[tid] = bi[nBase + tid]; }
        if (EPI == 1) { psc[tid] = sc[tid]; pbi[tid] = bi[tid]; pw3[tid] = W3[tid]; plg[tid] = 0.f; }
        if (EPI == 2) { pmax[tid] = 0u; }
    }

    float C[2][8][4];
#pragma unroll
    for (int mi = 0; mi < 2; mi++)
#pragma unroll
        for (int ni = 0; ni < 8; ni++)
#pragma unroll
            for (int q = 0; q < 4; q++) C[mi][ni][q] = 0.f;

    for (int kc = 0; kc < KTOT / 128; kc++) {
        // ---- A tile -> SMEM (hi/lo)
        if (ASRC == 0) {
            const float4 z4 = make_float4(0.f, 0.f, 0.f, 0.f);
            for (int i = tid; i < 4096; i += 256) {
                int r = i >> 5, c = (i & 31) << 2;
                int gr = rowBase + r;
                float4 v = (gr < NPTS) ? *(const float4*)&Af[(size_t)gr * KTOT + c] : z4;
                __nv_bfloat16 h0, h1, h2v, h3, l0, l1, l2, l3;
                bsplit(v.x, h0, l0); bsplit(v.y, h1, l1);
                bsplit(v.z, h2v, l2); bsplit(v.w, h3, l3);
                *(uint2*)&smAh[r * LDA + c] = make_uint2(pk(h0, h1), pk(h2v, h3));
                *(uint2*)&smAl[r * LDA + c] = make_uint2(pk(l0, l1), pk(l2, l3));
            }
        } else {
            const uint4 z4 = make_uint4(0u, 0u, 0u, 0u);
            for (int i = tid; i < 2048; i += 256) {
                int r = i >> 4, c8 = (i & 15) << 3;
                int gr = rowBase + r;
                uint4 vh = z4, vl = z4;
                if (gr < NPTS) {
                    vh = *(const uint4*)&Ahg[(size_t)gr * KTOT + kc * 128 + c8];
                    vl = *(const uint4*)&Alg[(size_t)gr * KTOT + kc * 128 + c8];
                }
                *(uint4*)&smAh[r * LDA + c8] = vh;
                *(uint4*)&smAl[r * LDA + c8] = vl;
            }
        }
        // ---- B tile -> SMEM
        for (int i = tid; i < 2048; i += 256) {
            int n = i >> 4, c8 = (i & 15) << 3;
            *(uint4*)&smBh[n * LDA + c8] =
                *(const uint4*)&Bhg[(size_t)(nBase + n) * KTOT + kc * 128 + c8];
            *(uint4*)&smBl[n * LDA + c8] =
                *(const uint4*)&Blg[(size_t)(nBase + n) * KTOT + kc * 128 + c8];
        }
        __syncthreads();

        // ---- 3-product split MMA: Ah*Bh + Ah*Bl + Al*Bh
#pragma unroll
        for (int p = 0; p < 3; p++) {
            const __nv_bfloat16* As = (p == 2) ? smAl : smAh;
            const __nv_bfloat16* Bs = (p == 1) ? smBl : smBh;
#pragma unroll
            for (int ks = 0; ks < 8; ks++) {
                const int k0 = ks * 16 + (t & 3) * 2;
                uint32_t bfr[8][2];
#pragma unroll
                for (int ni = 0; ni < 8; ni++) {
                    int n = warpN + ni * 8 + (t >> 2);
                    bfr[ni][0] = *(const uint32_t*)&Bs[n * LDA + k0];
                    bfr[ni][1] = *(const uint32_t*)&Bs[n * LDA + k0 + 8];
                }
#pragma unroll
                for (int mi = 0; mi < 2; mi++) {
                    int r = warpM + mi * 16 + (t >> 2);
                    uint32_t a0 = *(const uint32_t*)&As[r * LDA + k0];
                    uint32_t a1 = *(const uint32_t*)&As[(r + 8) * LDA + k0];
                    uint32_t a2 = *(const uint32_t*)&As[r * LDA + k0 + 8];
                    uint32_t a3 = *(const uint32_t*)&As[(r + 8) * LDA + k0 + 8];
#pragma unroll
                    for (int ni = 0; ni < 8; ni++)
                        hmma(C[mi][ni], a0, a1, a2, a3, bfr[ni][0], bfr[ni][1]);
                }
            }
        }
        __syncthreads();
    }

    // ---------------- epilogue ----------------
    const float b3v = (EPI == 1) ? b3[0] : 0.f;
#pragma unroll
    for (int mi = 0; mi < 2; mi++) {
        int lr = warpM + mi * 16 + (t >> 2);
        int gr0 = rowBase + lr, gr8 = gr0 + 8;
        float lp0 = 0.f, lp8 = 0.f;
#pragma unroll
        for (int ni = 0; ni < 8; ni++) {
            int lc = warpN + ni * 8 + (t & 3) * 2;
            float v0 = C[mi][ni][0], v1 = C[mi][ni][1];
            float v2 = C[mi][ni][2], v3 = C[mi][ni][3];
            if (EPI <= 1) {
                float s0 = psc[lc], s1v = psc[lc + 1], d0 = pbi[lc], d1 = pbi[lc + 1];
                v0 = fmaxf(v0 * s0 + d0, 0.f); v1 = fmaxf(v1 * s1v + d1, 0.f);
                v2 = fmaxf(v2 * s0 + d0, 0.f); v3 = fmaxf(v3 * s1v + d1, 0.f);
            }
            if (EPI == 0) {
                __nv_bfloat16 h0, h1, l0, l1;
                if (gr0 < NPTS) {
                    bsplit(v0, h0, l0); bsplit(v1, h1, l1);
                    size_t o = (size_t)gr0 * CH2 + nBase + lc;
                    *(uint32_t*)&g_Hh[o] = pk(h0, h1);
                    *(uint32_t*)&g_Hl[o] = pk(l0, l1);
                }
                if (gr8 < NPTS) {
                    bsplit(v2, h0, l0); bsplit(v3, h1, l1);
                    size_t o = (size_t)gr8 * CH2 + nBase + lc;
                    *(uint32_t*)&g_Hh[o] = pk(h0, h1);
                    *(uint32_t*)&g_Hl[o] = pk(l0, l1);
                }
            } else if (EPI == 1) {
                lp0 += v0 * pw3[lc] + v1 * pw3[lc + 1];
                lp8 += v2 * pw3[lc] + v3 * pw3[lc + 1];
                __nv_bfloat16 h0, h1, l0, l1;
                if (gr0 < NPTS) {
                    size_t o = (size_t)gr0 * CH + lc;
                    *(float2*)&g_h2[o] = make_float2(v0, v1);
                    bsplit(v0, h0, l0); bsplit(v1, h1, l1);
                    *(uint32_t*)&g_h2h[o] = pk(h0, h1);
                    *(uint32_t*)&g_h2l[o] = pk(l0, l1);
                }
                if (gr8 < NPTS) {
                    size_t o = (size_t)gr8 * CH + lc;
                    *(float2*)&g_h2[o] = make_float2(v2, v3);
                    bsplit(v2, h0, l0); bsplit(v3, h1, l1);
                    *(uint32_t*)&g_h2h[o] = pk(h0, h1);
                    *(uint32_t*)&g_h2l[o] = pk(l0, l1);
                }
            } else {
                if (gr0 < NPTS) *(float2*)&g_a[(size_t)gr0 * CH + lc] = make_float2(v0, v1);
                if (gr8 < NPTS) *(float2*)&g_a[(size_t)gr8 * CH + lc] = make_float2(v2, v3);
                unsigned e0 = 0u, e1 = 0u;
                if (gr0 < NPTS) { e0 = encf(v0); e1 = encf(v1); }
                if (gr8 < NPTS) {
                    unsigned f2 = encf(v2), f3 = encf(v3);
                    e0 = (f2 > e0) ? f2 : e0; e1 = (f3 > e1) ? f3 : e1;
                }
                if (e0) atomicMax(&pmax[lc], e0);
                if (e1) atomicMax(&pmax[lc + 1], e1);
            }
        }
        if (EPI == 1) { atomicAdd(&plg[lr], lp0); atomicAdd(&plg[lr + 8], lp8); }
    }
    if (EPI == 1) {
        __syncthreads();
        if (tid < 128 && rowBase + tid < NPTS) out[rowBase + tid] = plg[tid] + b3v;
    }
    if (EPI == 2) {
        __syncthreads();
        if (tid < 128) atomicMax(&g_cmax[tid], pmax[tid]);
    }
}

// ------------------------- sparse mask + attention accumulation --------------
__global__ void mask_accum(const float* __restrict__ xyz,
                           const float* __restrict__ center, const float* __restrict__ normal,
                           const float* __restrict__ pmin, const float* __restrict__ pmax,
                           const float* __restrict__ logit)
{
    __shared__ float4 sn[NPLANES];
    __shared__ float4 sbx[NPLANES];
    __shared__ float scm[CH];
    int tid = threadIdx.x;
    if (tid < NPLANES) {
        float nx = normal[tid * 3], ny = normal[tid * 3 + 1], nz = normal[tid * 3 + 2];
        float off = nx * center[tid * 3] + ny * center[tid * 3 + 1] + nz * center[tid * 3 + 2];
        sn[tid] = make_float4(nx, ny, nz, off);
        sbx[tid] = make_float4(pmin[tid * 3], pmin[tid * 3 + 1], pmax[tid * 3], pmax[tid * 3 + 1]);
    }
    if (tid < CH) scm[tid] = decf(g_cmax[tid]);
    __syncthreads();

    int n = blockIdx.x * blockDim.x + tid;
    unsigned long long m = 0ull;
    int sel = 0;
    if (n < NPTS) {
        float x = xyz[n * 3], y = xyz[n * 3 + 1], z = xyz[n * 3 + 2];
        sel = (logit[n] > 0.0f) ? 1 : 0;
        for (int p = 0; p < NPLANES; p++) {
            float4 nn = sn[p];
            float proj = x * nn.x + y * nn.y + z * nn.z;
            float4 bb = sbx[p];
            bool ok = (fabsf(proj - nn.w) < 0.1f) &&
                      (x >= bb.x) && (x < bb.z) && (y >= bb.y) && (y < bb.w);
            if (ok) m |= (1ull << p);
        }
    }

    int lane = tid & 31;
    for (;;) {
        unsigned act = __ballot_sync(0xffffffffu, m != 0ull);
        if (!act) break;
        int src = __ffs(act) - 1;
        unsigned long long ms = __shfl_sync(0xffffffffu, m, src);
        int ns  = __shfl_sync(0xffffffffu, n, src);
        int sls = __shfl_sync(0xffffffffu, sel, src);
        int p = __ffsll((long long)ms) - 1;
        if (lane == src) m &= (m - 1);

        float* num = g_num + ((sls ? 0 : 1) * NPLANES + p) * CH;
        float* den = g_den + ((sls ? 0 : 1) * NPLANES + p) * CH;
        const float* ar = g_a  + (size_t)ns * CH;
        const float* hr = g_h2 + (size_t)ns * CH;
#pragma unroll
        for (int i = 0; i < 4; i++) {
            int c = lane + 32 * i;
            float e = expf(ar[c] - scm[c]);
            atomicAdd(&num[c], e * hr[c]);
            atomicAdd(&den[c], e);
        }
    }
}

// ------------------------- finalize ------------------------------------------
__global__ void finalize_kernel(const float* __restrict__ Wm, const float* __restrict__ bm,
                                const float* __restrict__ center, const float* __restrict__ normal,
                                const float* __restrict__ pmin, const float* __restrict__ pmax,
                                float* __restrict__ out)
{
    int bp = blockIdx.x;
    int pool = bp >> 6, p = bp & 63;
    __shared__ float agg[CH];
    int j = threadIdx.x;
    int base = (pool * NPLANES + p) * CH;
    agg[j] = g_num[base + j] / (g_den[base + j] + 1e-9f);
    __syncthreads();

    float s = __ldg(&bm[j]);
#pragma unroll 8
    for (int c = 0; c < CH; c++) s += agg[c] * __ldg(&Wm[c * CH + j]);
    s = fmaxf(s, 0.f);

    float* ob = out + NPTS + (size_t)pool * NPLANES * FEAT_OUT + p * FEAT_OUT;
    ob[j] = s;
    if (j < 12) {
        float v;
        if (j < 3)      v = center[p * 3 + j];
        else if (j < 6) v = normal[p * 3 + (j - 3)];
        else if (j < 9) v = pmin[p * 3 + (j - 6)];
        else            v = pmax[p * 3 + (j - 9)];
        ob[CH + j] = v;
    }
}

// ------------------------- launch --------------------------------------------
extern "C" void kernel_launch(void* const* d_in, const int* in_sizes, int n_in,
                              void* d_out, int out_size)
{
    const float* feature = (const float*)d_in[0];
    const float* xyz     = (const float*)d_in[1];
    const float* center  = (const float*)d_in[2];
    const float* normal  = (const float*)d_in[3];
    const float* pmin    = (const float*)d_in[4];
    const float* pmax    = (const float*)d_in[5];
    const float* W1      = (const float*)d_in[6];
    const float* s1      = (const float*)d_in[7];
    const float* b1      = (const float*)d_in[8];
    const float* W2      = (const float*)d_in[9];
    const float* s2      = (const float*)d_in[10];
    const float* b2      = (const float*)d_in[11];
    const float* W3      = (const float*)d_in[12];
    const float* b3      = (const float*)d_in[13];
    const float* Wa      = (const float*)d_in[14];
    const float* Wm      = (const float*)d_in[15];
    const float* bm      = (const float*)d_in[16];
    float* out = (float*)d_out;

    __nv_bfloat16 *Hh, *Hl, *h2h, *h2l, *W1h, *W1l, *W2h, *W2l, *Wah, *Wal;
    cudaGetSymbolAddress((void**)&Hh,  g_Hh);
    cudaGetSymbolAddress((void**)&Hl,  g_Hl);
    cudaGetSymbolAddress((void**)&h2h, g_h2h);
    cudaGetSymbolAddress((void**)&h2l, g_h2l);
    cudaGetSymbolAddress((void**)&W1h, g_W1h);
    cudaGetSymbolAddress((void**)&W1l, g_W1l);
    cudaGetSymbolAddress((void**)&W2h, g_W2h);
    cudaGetSymbolAddress((void**)&W2l, g_W2l);
    cudaGetSymbolAddress((void**)&Wah, g_Wah);
    cudaGetSymbolAddress((void**)&Wal, g_Wal);

    cudaFuncSetAttribute(gemm_mma<128, 0, 0>, cudaFuncAttributeMaxDynamicSharedMemorySize, SMEM_TOT);
    cudaFuncSetAttribute(gemm_mma<256, 1, 1>, cudaFuncAttributeMaxDynamicSharedMemorySize, SMEM_TOT);
    cudaFuncSetAttribute(gemm_mma<128, 1, 2>, cudaFuncAttributeMaxDynamicSharedMemorySize, SMEM_TOT);

    const int MB = (NPTS + 127) / 128;   // 782

    init_kernel<<<64, 256>>>();
    prep_kernel<<<320, 256>>>(W1, W2, Wa);
    // fc1: H = relu((F@W1)*s1+b1) -> bf16 hi/lo
    gemm_mma<128, 0, 0><<<dim3(MB, 2), 256, SMEM_TOT>>>(
        feature, nullptr, nullptr, W1h, W1l, s1, b1, nullptr, nullptr, nullptr);
    // fc2: h2 = relu((H@W2)*s2+b2) (+ fused fc3 logit -> out[0:N))
    gemm_mma<256, 1, 1><<<dim3(MB, 1), 256, SMEM_TOT>>>(
        nullptr, Hh, Hl, W2h, W2l, s2, b2, W3, b3, out);
    // att: a = h2 @ Wa (+ per-channel colmax)
    gemm_mma<128, 1, 2><<<dim3(MB, 1), 256, SMEM_TOT>>>(
        nullptr, h2h, h2l, Wah, Wal, nullptr, nullptr, nullptr, nullptr, nullptr);
    mask_accum<<<(NPTS + 255) / 256, 256>>>(xyz, center, normal, pmin, pmax, out);
    finalize_kernel<<<128, 128>>>(Wm, bm, center, normal, pmin, pmax, out);
}

// round 11
// speedup vs baseline: 1.0025x; 1.0025x over previous
#include <cuda_runtime.h>
#include <cuda_bf16.h>
#include <math.h>
#include <stdint.h>

#define NPTS 100000
#define CH 128
#define CH2 256
#define NPLANES 64
#define FEAT_OUT 140

// ------------------------- scratch (__device__ globals) ----------------------
__device__ __nv_bfloat16 g_Hh [(size_t)NPTS * CH2];   // fc1 out hi
__device__ __nv_bfloat16 g_Hl [(size_t)NPTS * CH2];   // fc1 out lo
__device__ float         g_h2 [(size_t)NPTS * CH];    // fc2 out fp32
__device__ __nv_bfloat16 g_h2h[(size_t)NPTS * CH];    // fc2 out hi
__device__ __nv_bfloat16 g_h2l[(size_t)NPTS * CH];    // fc2 out lo
__device__ float         g_a  [(size_t)NPTS * CH];    // attention activations
__device__ float g_num[2 * NPLANES * CH];
__device__ float g_den[2 * NPLANES * CH];
__device__ unsigned g_cmax[CH];

// pre-split weights, [n][k] layout (bf16 hi/lo)
__device__ __nv_bfloat16 g_W1h[CH2 * CH], g_W1l[CH2 * CH];
__device__ __nv_bfloat16 g_W2h[CH * CH2], g_W2l[CH * CH2];
__device__ __nv_bfloat16 g_Wah[CH * CH],  g_Wal[CH * CH];

__device__ __forceinline__ unsigned encf(float f) {
    unsigned u = __float_as_uint(f);
    return (u & 0x80000000u) ? ~u : (u | 0x80000000u);
}
__device__ __forceinline__ float decf(unsigned u) {
    return __uint_as_float((u & 0x80000000u) ? (u & 0x7fffffffu) : ~u);
}
__device__ __forceinline__ uint32_t pk(__nv_bfloat16 a, __nv_bfloat16 b) {
    return ((uint32_t)__bfloat16_as_ushort(b) << 16) | (uint32_t)__bfloat16_as_ushort(a);
}
__device__ __forceinline__ void bsplit(float f, __nv_bfloat16& h, __nv_bfloat16& l) {
    h = __float2bfloat16(f);
    l = __float2bfloat16(f - __bfloat162float(h));
}

__global__ void init_kernel() {
    int t = blockIdx.x * blockDim.x + threadIdx.x;
    if (t < 2 * NPLANES * CH) { g_num[t] = 0.f; g_den[t] = 0.f; }
    if (t < CH) g_cmax[t] = encf(-3.0e38f);
}

// ---------------- weight pre-split: W[k][n] fp32 -> [n][k] bf16 hi/lo --------
__global__ void prep_kernel(const float* __restrict__ W1, const float* __restrict__ W2,
                            const float* __restrict__ Wa)
{
    int t = blockIdx.x * blockDim.x + threadIdx.x;
    __nv_bfloat16 h, l;
    if (t < 32768) {
        int n = t >> 7, k = t & 127;
        bsplit(W1[k * CH2 + n], h, l);
        g_W1h[t] = h; g_W1l[t] = l;
    } else if (t < 65536) {
        int u = t - 32768;
        int n = u >> 8, k = u & 255;
        bsplit(W2[k * CH + n], h, l);
        g_W2h[u] = h; g_W2l[u] = l;
    } else if (t < 81920) {
        int u = t - 65536;
        int n = u >> 7, k = u & 127;
        bsplit(Wa[k * CH + n], h, l);
        g_Wah[u] = h; g_Wal[u] = l;
    }
}

// ------------------------- MMA primitives ------------------------------------
__device__ __forceinline__ void hmma(float* c, uint32_t a0, uint32_t a1,
                                     uint32_t a2, uint32_t a3,
                                     uint32_t b0, uint32_t b1) {
    asm("mma.sync.aligned.m16n8k16.row.col.f32.bf16.bf16.f32 "
        "{%0,%1,%2,%3},{%4,%5,%6,%7},{%8,%9},{%0,%1,%2,%3};"
        : "+f"(c[0]), "+f"(c[1]), "+f"(c[2]), "+f"(c[3])
        : "r"(a0), "r"(a1), "r"(a2), "r"(a3), "r"(b0), "r"(b1));
}
__device__ __forceinline__ void ldsm4(uint32_t* r, uint32_t saddr) {
    asm volatile("ldmatrix.sync.aligned.m8n8.x4.shared.b16 {%0,%1,%2,%3}, [%4];"
                 : "=r"(r[0]), "=r"(r[1]), "=r"(r[2]), "=r"(r[3]) : "r"(saddr));
}

// ------------------------- SMEM layout ---------------------------------------
#define LDA 136                           // 128 + 8 halves pad: LDSM conflict-free
#define A_BYTES (128 * LDA * 2)           // 34816
#define OFF_AH  0
#define OFF_AL  A_BYTES
#define OFF_BH  (2 * A_BYTES)
#define OFF_BL  (3 * A_BYTES)
#define OFF_PAR (4 * A_BYTES)
#define SMEM_TOT (OFF_PAR + 2048)         // 141312

// ============================================================================
// gemm_mma<KTOT, ASRC, EPI>  (512 threads, 16 warps, warp tile 32x32)
//   ASRC 0: A fp32 gmem (convert+split inline);  1: A prestored bf16 hi/lo
//   EPI 0: relu(acc*s+b) -> g_Hh/g_Hl       (fc1)
//   EPI 1: relu(acc*s+b) -> g_h2 + hi/lo, fused fc3 logit -> out   (fc2)
//   EPI 2: raw -> g_a, per-channel colmax -> g_cmax                 (att)
// ============================================================================
template <int KTOT, int ASRC, int EPI>
__global__ __launch_bounds__(512, 1)
void gemm_mma(const float* __restrict__ Af,
              const __nv_bfloat16* __restrict__ Ahg, const __nv_bfloat16* __restrict__ Alg,
              const __nv_bfloat16* __restrict__ Bhg, const __nv_bfloat16* __restrict__ Blg,
              const float* __restrict__ sc, const float* __restrict__ bi,
              const float* __restrict__ W3, const float* __restrict__ b3,
              float* __restrict__ out)
{
    extern __shared__ __align__(16) char smx[];
    __nv_bfloat16* smAh = (__nv_bfloat16*)(smx + OFF_AH);
    __nv_bfloat16* smAl = (__nv_bfloat16*)(smx + OFF_AL);
    __nv_bfloat16* smBh = (__nv_bfloat16*)(smx + OFF_BH);
    __nv_bfloat16* smBl = (__nv_bfloat16*)(smx + OFF_BL);
    float* par = (float*)(smx + OFF_PAR);
    float* psc = par;          float* pbi = par + 128;
    float* pw3 = par + 256;    float* plg = par + 384;
    unsigned* pmax = (unsigned*)(par + 384);

    const int tid = threadIdx.x, wid = tid >> 5, t = tid & 31;
    const int rowBase = blockIdx.x * 128, nBase = blockIdx.y * 128;
    const int warpM = (wid & 3) * 32, warpN = (wid >> 2) * 32;

    if (tid < 128) {
        if (EPI == 0) { psc[tid] = sc[nBase + tid]; pbi[tid] = bi[nBase + tid]; }
        if (EPI == 1) { psc[tid] = sc[tid]; pbi[tid] = bi[tid]; pw3[tid] = W3[tid]; plg[tid] = 0.f; }
        if (EPI == 2) { pmax[tid] = 0u; }
    }

    // ldmatrix per-thread byte offsets within a tile buffer
    const int g = t >> 3;
    uint32_t aOff[2], bOff[2];
#pragma unroll
    for (int mi = 0; mi < 2; mi++) {
        int row = warpM + mi * 16 + (g & 1) * 8 + (t & 7);
        int col = (g >> 1) * 8;
        aOff[mi] = (uint32_t)(row * LDA + col) * 2;
    }
#pragma unroll
    for (int nb = 0; nb < 2; nb++) {
        int row = warpN + nb * 16 + (g >> 1) * 8 + (t & 7);
        int col = (g & 1) * 8;
        bOff[nb] = (uint32_t)(row * LDA + col) * 2;
    }
    const uint32_t sbase = (uint32_t)__cvta_generic_to_shared(smx);
    const uint32_t pA[3] = { sbase + OFF_AH, sbase + OFF_AH, sbase + OFF_AL };
    const uint32_t pB[3] = { sbase + OFF_BH, sbase + OFF_BL, sbase + OFF_BH };

    float C[2][4][4];
#pragma unroll
    for (int mi = 0; mi < 2; mi++)
#pragma unroll
        for (int ni = 0; ni < 4; ni++)
#pragma unroll
            for (int q = 0; q < 4; q++) C[mi][ni][q] = 0.f;

    for (int kc = 0; kc < KTOT / 128; kc++) {
        // ---- A tile -> SMEM (hi/lo)
        if (ASRC == 0) {
            const float4 z4 = make_float4(0.f, 0.f, 0.f, 0.f);
            for (int i = tid; i < 4096; i += 512) {
                int r = i >> 5, c = (i & 31) << 2;
                int gr = rowBase + r;
                float4 v = (gr < NPTS) ? *(const float4*)&Af[(size_t)gr * KTOT + c] : z4;
                __nv_bfloat16 h0, h1, h2v, h3, l0, l1, l2, l3;
                bsplit(v.x, h0, l0); bsplit(v.y, h1, l1);
                bsplit(v.z, h2v, l2); bsplit(v.w, h3, l3);
                *(uint2*)&smAh[r * LDA + c] = make_uint2(pk(h0, h1), pk(h2v, h3));
                *(uint2*)&smAl[r * LDA + c] = make_uint2(pk(l0, l1), pk(l2, l3));
            }
        } else {
            const uint4 z4 = make_uint4(0u, 0u, 0u, 0u);
            for (int i = tid; i < 2048; i += 512) {
                int r = i >> 4, c8 = (i & 15) << 3;
                int gr = rowBase + r;
                uint4 vh = z4, vl = z4;
                if (gr < NPTS) {
                    vh = *(const uint4*)&Ahg[(size_t)gr * KTOT + kc * 128 + c8];
                    vl = *(const uint4*)&Alg[(size_t)gr * KTOT + kc * 128 + c8];
                }
                *(uint4*)&smAh[r * LDA + c8] = vh;
                *(uint4*)&smAl[r * LDA + c8] = vl;
            }
        }
        // ---- B tile -> SMEM
        for (int i = tid; i < 2048; i += 512) {
            int n = i >> 4, c8 = (i & 15) << 3;
            *(uint4*)&smBh[n * LDA + c8] =
                *(const uint4*)&Bhg[(size_t)(nBase + n) * KTOT + kc * 128 + c8];
            *(uint4*)&smBl[n * LDA + c8] =
                *(const uint4*)&Blg[(size_t)(nBase + n) * KTOT + kc * 128 + c8];
        }
        __syncthreads();

        // ---- pipelined 3-product split: Ah*Bh + Ah*Bl + Al*Bh (24 steps)
        uint32_t Afr[2][2][4], Bfr[2][2][4];
        ldsm4(Afr[0][0], pA[0] + aOff[0]);
        ldsm4(Afr[0][1], pA[0] + aOff[1]);
        ldsm4(Bfr[0][0], pB[0] + bOff[0]);
        ldsm4(Bfr[0][1], pB[0] + bOff[1]);
#pragma unroll
        for (int s = 0; s < 24; s++) {
            const int cur = s & 1, nxt = cur ^ 1;
            if (s < 23) {
                const int s1 = s + 1;
                const uint32_t ko = (uint32_t)(s1 & 7) * 32;
                const uint32_t ba = pA[s1 >> 3] + ko, bb = pB[s1 >> 3] + ko;
                ldsm4(Afr[nxt][0], ba + aOff[0]);
                ldsm4(Afr[nxt][1], ba + aOff[1]);
                ldsm4(Bfr[nxt][0], bb + bOff[0]);
                ldsm4(Bfr[nxt][1], bb + bOff[1]);
            }
#pragma unroll
            for (int mi = 0; mi < 2; mi++)
#pragma unroll
                for (int ni = 0; ni < 4; ni++)
                    hmma(C[mi][ni],
                         Afr[cur][mi][0], Afr[cur][mi][1], Afr[cur][mi][2], Afr[cur][mi][3],
                         Bfr[cur][ni >> 1][(ni & 1) * 2], Bfr[cur][ni >> 1][(ni & 1) * 2 + 1]);
        }
        __syncthreads();
    }

    // ---------------- epilogue ----------------
    const float b3v = (EPI == 1) ? b3[0] : 0.f;
#pragma unroll
    for (int mi = 0; mi < 2; mi++) {
        int lr = warpM + mi * 16 + (t >> 2);
        int gr0 = rowBase + lr, gr8 = gr0 + 8;
        float lp0 = 0.f, lp8 = 0.f;
#pragma unroll
        for (int ni = 0; ni < 4; ni++) {
            int lc = warpN + ni * 8 + (t & 3) * 2;
            float v0 = C[mi][ni][0], v1 = C[mi][ni][1];
            float v2 = C[mi][ni][2], v3 = C[mi][ni][3];
            if (EPI <= 1) {
                float s0 = psc[lc], s1v = psc[lc + 1], d0 = pbi[lc], d1 = pbi[lc + 1];
                v0 = fmaxf(v0 * s0 + d0, 0.f); v1 = fmaxf(v1 * s1v + d1, 0.f);
                v2 = fmaxf(v2 * s0 + d0, 0.f); v3 = fmaxf(v3 * s1v + d1, 0.f);
            }
            if (EPI == 0) {
                __nv_bfloat16 h0, h1, l0, l1;
                if (gr0 < NPTS) {
                    bsplit(v0, h0, l0); bsplit(v1, h1, l1);
                    size_t o = (size_t)gr0 * CH2 + nBase + lc;
                    *(uint32_t*)&g_Hh[o] = pk(h0, h1);
                    *(uint32_t*)&g_Hl[o] = pk(l0, l1);
                }
                if (gr8 < NPTS) {
                    bsplit(v2, h0, l0); bsplit(v3, h1, l1);
                    size_t o = (size_t)gr8 * CH2 + nBase + lc;
                    *(uint32_t*)&g_Hh[o] = pk(h0, h1);
                    *(uint32_t*)&g_Hl[o] = pk(l0, l1);
                }
            } else if (EPI == 1) {
                lp0 += v0 * pw3[lc] + v1 * pw3[lc + 1];
                lp8 += v2 * pw3[lc] + v3 * pw3[lc + 1];
                __nv_bfloat16 h0, h1, l0, l1;
                if (gr0 < NPTS) {
                    size_t o = (size_t)gr0 * CH + lc;
                    *(float2*)&g_h2[o] = make_float2(v0, v1);
                    bsplit(v0, h0, l0); bsplit(v1, h1, l1);
                    *(uint32_t*)&g_h2h[o] = pk(h0, h1);
                    *(uint32_t*)&g_h2l[o] = pk(l0, l1);
                }
                if (gr8 < NPTS) {
                    size_t o = (size_t)gr8 * CH + lc;
                    *(float2*)&g_h2[o] = make_float2(v2, v3);
                    bsplit(v2, h0, l0); bsplit(v3, h1, l1);
                    *(uint32_t*)&g_h2h[o] = pk(h0, h1);
                    *(uint32_t*)&g_h2l[o] = pk(l0, l1);
                }
            } else {
                if (gr0 < NPTS) *(float2*)&g_a[(size_t)gr0 * CH + lc] = make_float2(v0, v1);
                if (gr8 < NPTS) *(float2*)&g_a[(size_t)gr8 * CH + lc] = make_float2(v2, v3);
                unsigned e0 = 0u, e1 = 0u;
                if (gr0 < NPTS) { e0 = encf(v0); e1 = encf(v1); }
                if (gr8 < NPTS) {
                    unsigned f2 = encf(v2), f3 = encf(v3);
                    e0 = (f2 > e0) ? f2 : e0; e1 = (f3 > e1) ? f3 : e1;
                }
                if (e0) atomicMax(&pmax[lc], e0);
                if (e1) atomicMax(&pmax[lc + 1], e1);
            }
        }
        if (EPI == 1) { atomicAdd(&plg[lr], lp0); atomicAdd(&plg[lr + 8], lp8); }
    }
    if (EPI == 1) {
        __syncthreads();
        if (tid < 128 && rowBase + tid < NPTS) out[rowBase + tid] = plg[tid] + b3v;
    }
    if (EPI == 2) {
        __syncthreads();
        if (tid < 128) atomicMax(&g_cmax[tid], pmax[tid]);
    }
}

// ------------------------- sparse mask + attention accumulation --------------
__global__ void mask_accum(const float* __restrict__ xyz,
                           const float* __restrict__ center, const float* __restrict__ normal,
                           const float* __restrict__ pmin, const float* __restrict__ pmax,
                           const float* __restrict__ logit)
{
    __shared__ float4 sn[NPLANES];
    __shared__ float4 sbx[NPLANES];
    __shared__ float scm[CH];
    int tid = threadIdx.x;
    if (tid < NPLANES) {
        float nx = normal[tid * 3], ny = normal[tid * 3 + 1], nz = normal[tid * 3 + 2];
        float off = nx * center[tid * 3] + ny * center[tid * 3 + 1] + nz * center[tid * 3 + 2];
        sn[tid] = make_float4(nx, ny, nz, off);
        sbx[tid] = make_float4(pmin[tid * 3], pmin[tid * 3 + 1], pmax[tid * 3], pmax[tid * 3 + 1]);
    }
    if (tid < CH) scm[tid] = decf(g_cmax[tid]);
    __syncthreads();

    int n = blockIdx.x * blockDim.x + tid;
    unsigned long long m = 0ull;
    int sel = 0;
    if (n < NPTS) {
        float x = xyz[n * 3], y = xyz[n * 3 + 1], z = xyz[n * 3 + 2];
        sel = (logit[n] > 0.0f) ? 1 : 0;
        for (int p = 0; p < NPLANES; p++) {
            float4 nn = sn[p];
            float proj = x * nn.x + y * nn.y + z * nn.z;
            float4 bb = sbx[p];
            bool ok = (fabsf(proj - nn.w) < 0.1f) &&
                      (x >= bb.x) && (x < bb.z) && (y >= bb.y) && (y < bb.w);
            if (ok) m |= (1ull << p);
        }
    }

    int lane = tid & 31;
    for (;;) {
        unsigned act = __ballot_sync(0xffffffffu, m != 0ull);
        if (!act) break;
        int src = __ffs(act) - 1;
        unsigned long long ms = __shfl_sync(0xffffffffu, m, src);
        int ns  = __shfl_sync(0xffffffffu, n, src);
        int sls = __shfl_sync(0xffffffffu, sel, src);
        int p = __ffsll((long long)ms) - 1;
        if (lane == src) m &= (m - 1);

        float* num = g_num + ((sls ? 0 : 1) * NPLANES + p) * CH;
        float* den = g_den + ((sls ? 0 : 1) * NPLANES + p) * CH;
        const float* ar = g_a  + (size_t)ns * CH;
        const float* hr = g_h2 + (size_t)ns * CH;
#pragma unroll
        for (int i = 0; i < 4; i++) {
            int c = lane + 32 * i;
            float e = expf(ar[c] - scm[c]);
            atomicAdd(&num[c], e * hr[c]);
            atomicAdd(&den[c], e);
        }
    }
}

// ------------------------- finalize ------------------------------------------
__global__ void finalize_kernel(const float* __restrict__ Wm, const float* __restrict__ bm,
                                const float* __restrict__ center, const float* __restrict__ normal,
                                const float* __restrict__ pmin, const float* __restrict__ pmax,
                                float* __restrict__ out)
{
    int bp = blockIdx.x;
    int pool = bp >> 6, p = bp & 63;
    __shared__ float agg[CH];
    int j = threadIdx.x;
    int base = (pool * NPLANES + p) * CH;
    agg[j] = g_num[base + j] / (g_den[base + j] + 1e-9f);
    __syncthreads();

    float s = __ldg(&bm[j]);
#pragma unroll 8
    for (int c = 0; c < CH; c++) s += agg[c] * __ldg(&Wm[c * CH + j]);
    s = fmaxf(s, 0.f);

    float* ob = out + NPTS + (size_t)pool * NPLANES * FEAT_OUT + p * FEAT_OUT;
    ob[j] = s;
    if (j < 12) {
        float v;
        if (j < 3)      v = center[p * 3 + j];
        else if (j < 6) v = normal[p * 3 + (j - 3)];
        else if (j < 9) v = pmin[p * 3 + (j - 6)];
        else            v = pmax[p * 3 + (j - 9)];
        ob[CH + j] = v;
    }
}

// ------------------------- launch --------------------------------------------
extern "C" void kernel_launch(void* const* d_in, const int* in_sizes, int n_in,
                              void* d_out, int out_size)
{
    const float* feature = (const float*)d_in[0];
    const float* xyz     = (const float*)d_in[1];
    const float* center  = (const float*)d_in[2];
    const float* normal  = (const float*)d_in[3];
    const float* pmin    = (const float*)d_in[4];
    const float* pmax    = (const float*)d_in[5];
    const float* W1      = (const float*)d_in[6];
    const float* s1      = (const float*)d_in[7];
    const float* b1      = (const float*)d_in[8];
    const float* W2      = (const float*)d_in[9];
    const float* s2      = (const float*)d_in[10];
    const float* b2      = (const float*)d_in[11];
    const float* W3      = (const float*)d_in[12];
    const float* b3      = (const float*)d_in[13];
    const float* Wa      = (const float*)d_in[14];
    const float* Wm      = (const float*)d_in[15];
    const float* bm      = (const float*)d_in[16];
    float* out = (float*)d_out;

    __nv_bfloat16 *Hh, *Hl, *h2h, *h2l, *W1h, *W1l, *W2h, *W2l, *Wah, *Wal;
    cudaGetSymbolAddress((void**)&Hh,  g_Hh);
    cudaGetSymbolAddress((void**)&Hl,  g_Hl);
    cudaGetSymbolAddress((void**)&h2h, g_h2h);
    cudaGetSymbolAddress((void**)&h2l, g_h2l);
    cudaGetSymbolAddress((void**)&W1h, g_W1h);
    cudaGetSymbolAddress((void**)&W1l, g_W1l);
    cudaGetSymbolAddress((void**)&W2h, g_W2h);
    cudaGetSymbolAddress((void**)&W2l, g_W2l);
    cudaGetSymbolAddress((void**)&Wah, g_Wah);
    cudaGetSymbolAddress((void**)&Wal, g_Wal);

    cudaFuncSetAttribute(gemm_mma<128, 0, 0>, cudaFuncAttributeMaxDynamicSharedMemorySize, SMEM_TOT);
    cudaFuncSetAttribute(gemm_mma<256, 1, 1>, cudaFuncAttributeMaxDynamicSharedMemorySize, SMEM_TOT);
    cudaFuncSetAttribute(gemm_mma<128, 1, 2>, cudaFuncAttributeMaxDynamicSharedMemorySize, SMEM_TOT);

    const int MB = (NPTS + 127) / 128;   // 782

    init_kernel<<<64, 256>>>();
    prep_kernel<<<320, 256>>>(W1, W2, Wa);
    gemm_mma<128, 0, 0><<<dim3(MB, 2), 512, SMEM_TOT>>>(
        feature, nullptr, nullptr, W1h, W1l, s1, b1, nullptr, nullptr, nullptr);
    gemm_mma<256, 1, 1><<<dim3(MB, 1), 512, SMEM_TOT>>>(
        nullptr, Hh, Hl, W2h, W2l, s2, b2, W3, b3, out);
    gemm_mma<128, 1, 2><<<dim3(MB, 1), 512, SMEM_TOT>>>(
        nullptr, h2h, h2l, Wah, Wal, nullptr, nullptr, nullptr, nullptr, nullptr);
    mask_accum<<<(NPTS + 255) / 256, 256>>>(xyz, center, normal, pmin, pmax, out);
    finalize_kernel<<<128, 128>>>(Wm, bm, center, normal, pmin, pmax, out);
}

// round 12
// speedup vs baseline: 1.4000x; 1.3965x over previous
#include <cuda_runtime.h>
#include <cuda_bf16.h>
#include <math.h>
#include <stdint.h>

#define NPTS 100000
#define CH 128
#define CH2 256
#define NPLANES 64
#define FEAT_OUT 140

// ------------------------- scratch (__device__ globals) ----------------------
__device__ __nv_bfloat16 g_Hh [(size_t)NPTS * CH2];
__device__ __nv_bfloat16 g_Hl [(size_t)NPTS * CH2];
__device__ float         g_h2 [(size_t)NPTS * CH];
__device__ __nv_bfloat16 g_h2h[(size_t)NPTS * CH];
__device__ __nv_bfloat16 g_h2l[(size_t)NPTS * CH];
__device__ float         g_a  [(size_t)NPTS * CH];
__device__ float g_num[2 * NPLANES * CH];
__device__ float g_den[2 * NPLANES * CH];
__device__ unsigned g_cmax[CH];

__device__ __nv_bfloat16 g_W1h[CH2 * CH], g_W1l[CH2 * CH];
__device__ __nv_bfloat16 g_W2h[CH * CH2], g_W2l[CH * CH2];
__device__ __nv_bfloat16 g_Wah[CH * CH],  g_Wal[CH * CH];

__device__ __forceinline__ unsigned encf(float f) {
    unsigned u = __float_as_uint(f);
    return (u & 0x80000000u) ? ~u : (u | 0x80000000u);
}
__device__ __forceinline__ float decf(unsigned u) {
    return __uint_as_float((u & 0x80000000u) ? (u & 0x7fffffffu) : ~u);
}
__device__ __forceinline__ uint32_t pk(__nv_bfloat16 a, __nv_bfloat16 b) {
    return ((uint32_t)__bfloat16_as_ushort(b) << 16) | (uint32_t)__bfloat16_as_ushort(a);
}
__device__ __forceinline__ void bsplit(float f, __nv_bfloat16& h, __nv_bfloat16& l) {
    h = __float2bfloat16(f);
    l = __float2bfloat16(f - __bfloat162float(h));
}

__global__ void init_kernel() {
    int t = blockIdx.x * blockDim.x + threadIdx.x;
    if (t < 2 * NPLANES * CH) { g_num[t] = 0.f; g_den[t] = 0.f; }
    if (t < CH) g_cmax[t] = encf(-3.0e38f);
}

__global__ void prep_kernel(const float* __restrict__ W1, const float* __restrict__ W2,
                            const float* __restrict__ Wa)
{
    int t = blockIdx.x * blockDim.x + threadIdx.x;
    __nv_bfloat16 h, l;
    if (t < 32768) {
        int n = t >> 7, k = t & 127;
        bsplit(W1[k * CH2 + n], h, l);
        g_W1h[t] = h; g_W1l[t] = l;
    } else if (t < 65536) {
        int u = t - 32768;
        int n = u >> 8, k = u & 255;
        bsplit(W2[k * CH + n], h, l);
        g_W2h[u] = h; g_W2l[u] = l;
    } else if (t < 81920) {
        int u = t - 65536;
        int n = u >> 7, k = u & 127;
        bsplit(Wa[k * CH + n], h, l);
        g_Wah[u] = h; g_Wal[u] = l;
    }
}

// ------------------------- primitives ----------------------------------------
__device__ __forceinline__ void hmma(float* c, const uint32_t* a,
                                     uint32_t b0, uint32_t b1) {
    asm("mma.sync.aligned.m16n8k16.row.col.f32.bf16.bf16.f32 "
        "{%0,%1,%2,%3},{%4,%5,%6,%7},{%8,%9},{%0,%1,%2,%3};"
        : "+f"(c[0]), "+f"(c[1]), "+f"(c[2]), "+f"(c[3])
        : "r"(a[0]), "r"(a[1]), "r"(a[2]), "r"(a[3]), "r"(b0), "r"(b1));
}
__device__ __forceinline__ void ldsm4(uint32_t* r, uint32_t saddr) {
    asm volatile("ldmatrix.sync.aligned.m8n8.x4.shared.b16 {%0,%1,%2,%3}, [%4];"
                 : "=r"(r[0]), "=r"(r[1]), "=r"(r[2]), "=r"(r[3]) : "r"(saddr));
}
__device__ __forceinline__ void cpa16(uint32_t dst, const void* src, int sz) {
    asm volatile("cp.async.cg.shared.global [%0], [%1], 16, %2;"
                 :: "r"(dst), "l"(src), "r"(sz) : "memory");
}
__device__ __forceinline__ void cpa_wait() {
    asm volatile("cp.async.commit_group;\n\tcp.async.wait_group 0;" ::: "memory");
}

// XOR swizzle: 16B chunk c within a row of RB bytes; conflict-free for ldmatrix
__device__ __forceinline__ uint32_t swz(int row, int c, int RB) {
    return (uint32_t)(row * RB + (((c ^ (row & 7)) << 4)));
}

// ============================================================================
// gemm_mma<KTOT, ASRC, EPI>  (512 threads, 16 warps, warp tile 32x32)
//   B fully resident in SMEM (swizzled); A staged per 128-K chunk (cp.async)
//   ASRC 0: A fp32 gmem (convert+split inline);  1: A prestored bf16 hi/lo
//   EPI 0: relu(acc*s+b) -> g_Hh/g_Hl (fc1)
//   EPI 1: relu(acc*s+b) -> g_h2 + hi/lo, fused fc3 logit -> out (fc2)
//   EPI 2: raw -> g_a, colmax -> g_cmax (att)
// ============================================================================
template <int KTOT, int ASRC, int EPI>
__global__ __launch_bounds__(512, 1)
void gemm_mma(const float* __restrict__ Af,
              const __nv_bfloat16* __restrict__ Ahg, const __nv_bfloat16* __restrict__ Alg,
              const __nv_bfloat16* __restrict__ Bhg, const __nv_bfloat16* __restrict__ Blg,
              const float* __restrict__ sc, const float* __restrict__ bi,
              const float* __restrict__ W3, const float* __restrict__ b3,
              float* __restrict__ out)
{
    constexpr int RBB   = KTOT * 2;          // B row bytes
    constexpr int BMAT  = 128 * RBB;         // one B matrix bytes
    constexpr int OFF_BH = 0;
    constexpr int OFF_BL = BMAT;
    constexpr int OFF_AH = 2 * BMAT;
    constexpr int OFF_AL = OFF_AH + 32768;   // A chunk matrix = 128*256B
    constexpr int OFF_PAR = OFF_AL + 32768;
    constexpr int BCPR  = KTOT / 8;          // 16B chunks per B row

    extern __shared__ __align__(16) char smx[];
    float* par = (float*)(smx + OFF_PAR);
    float* psc = par;          float* pbi = par + 128;
    float* pw3 = par + 256;    float* plg = par + 384;
    unsigned* pmax = (unsigned*)(par + 384);

    const int tid = threadIdx.x, wid = tid >> 5, t = tid & 31;
    const int rowBase = blockIdx.x * 128, nBase = blockIdx.y * 128;
    const int warpM = (wid & 3) * 32, warpN = (wid >> 2) * 32;

    if (tid < 128) {
        if (EPI == 0) { psc[tid] = sc[nBase + tid]; pbi[tid] = bi[nBase + tid]; }
        if (EPI == 1) { psc[tid] = sc[tid]; pbi[tid] = bi[tid]; pw3[tid] = W3[tid]; plg[tid] = 0.f; }
        if (EPI == 2) { pmax[tid] = 0u; }
    }

    const uint32_t sbase = (uint32_t)__cvta_generic_to_shared(smx);
    const uint32_t sBH = sbase + OFF_BH, sBL = sbase + OFF_BL;
    const uint32_t sAH = sbase + OFF_AH, sAL = sbase + OFF_AL;

    // ---- B resident load (cp.async, once)
    for (int i = tid; i < 128 * BCPR; i += 512) {
        int n = i / BCPR, c = i % BCPR;
        const size_t gsrc = (size_t)(nBase + n) * KTOT + c * 8;
        cpa16(sBH + swz(n, c, RBB), Bhg + gsrc, 16);
        cpa16(sBL + swz(n, c, RBB), Blg + gsrc, 16);
    }
    // ---- A chunk 0
    if (ASRC == 1) {
        for (int i = tid; i < 2048; i += 512) {
            int r = i >> 4, c = i & 15;
            int gr = rowBase + r;
            int sz = (gr < NPTS) ? 16 : 0;
            int grc = (gr < NPTS) ? gr : (NPTS - 1);
            const size_t gsrc = (size_t)grc * KTOT + c * 8;
            cpa16(sAH + swz(r, c, 256), Ahg + gsrc, sz);
            cpa16(sAL + swz(r, c, 256), Alg + gsrc, sz);
        }
        cpa_wait();
    } else {
        cpa_wait();   // B only
        const float4 z4 = make_float4(0.f, 0.f, 0.f, 0.f);
        __nv_bfloat16* smAh = (__nv_bfloat16*)(smx + OFF_AH);
        __nv_bfloat16* smAl = (__nv_bfloat16*)(smx + OFF_AL);
        for (int i = tid; i < 4096; i += 512) {
            int r = i >> 5, c4 = i & 31;
            int gr = rowBase + r;
            float4 v = (gr < NPTS) ? *(const float4*)&Af[(size_t)gr * KTOT + c4 * 4] : z4;
            __nv_bfloat16 h0, h1, h2v, h3, l0, l1, l2, l3;
            bsplit(v.x, h0, l0); bsplit(v.y, h1, l1);
            bsplit(v.z, h2v, l2); bsplit(v.w, h3, l3);
            uint32_t off = swz(r, c4 >> 1, 256) + (c4 & 1) * 8;
            *(uint2*)((char*)smAh + off) = make_uint2(pk(h0, h1), pk(h2v, h3));
            *(uint2*)((char*)smAl + off) = make_uint2(pk(l0, l1), pk(l2, l3));
        }
    }
    __syncthreads();

    // ldmatrix per-thread row coordinates
    const int g = t >> 3;
    const int rA0 = warpM + (g & 1) * 8 + (t & 7);        // + mi*16
    const int cgA = g >> 1;
    const int rB0 = warpN + (g >> 1) * 8 + (t & 7);       // + nb*16
    const int cgB = g & 1;

    float C[2][4][4];
#pragma unroll
    for (int mi = 0; mi < 2; mi++)
#pragma unroll
        for (int ni = 0; ni < 4; ni++)
#pragma unroll
            for (int q = 0; q < 4; q++) C[mi][ni][q] = 0.f;

    for (int kc = 0; kc < KTOT / 128; kc++) {
#pragma unroll
        for (int s = 0; s < 8; s++) {
            uint32_t Ah[2][4], Al[2][4], Bh[2][4], Bl[2][4];
            const int sg = kc * 8 + s;
#pragma unroll
            for (int mi = 0; mi < 2; mi++) {
                int row = rA0 + mi * 16;
                uint32_t o = swz(row, 2 * s + cgA, 256);
                ldsm4(Ah[mi], sAH + o);
                ldsm4(Al[mi], sAL + o);
            }
#pragma unroll
            for (int nb = 0; nb < 2; nb++) {
                int row = rB0 + nb * 16;
                uint32_t o = swz(row, 2 * sg + cgB, RBB);
                ldsm4(Bh[nb], sBH + o);
                ldsm4(Bl[nb], sBL + o);
            }
#pragma unroll
            for (int mi = 0; mi < 2; mi++)
#pragma unroll
                for (int ni = 0; ni < 4; ni++)
                    hmma(C[mi][ni], Ah[mi], Bh[ni >> 1][(ni & 1) * 2], Bh[ni >> 1][(ni & 1) * 2 + 1]);
#pragma unroll
            for (int mi = 0; mi < 2; mi++)
#pragma unroll
                for (int ni = 0; ni < 4; ni++)
                    hmma(C[mi][ni], Ah[mi], Bl[ni >> 1][(ni & 1) * 2], Bl[ni >> 1][(ni & 1) * 2 + 1]);
#pragma unroll
            for (int mi = 0; mi < 2; mi++)
#pragma unroll
                for (int ni = 0; ni < 4; ni++)
                    hmma(C[mi][ni], Al[mi], Bh[ni >> 1][(ni & 1) * 2], Bh[ni >> 1][(ni & 1) * 2 + 1]);
        }
        // next A chunk
        if (kc + 1 < KTOT / 128) {
            __syncthreads();
            for (int i = tid; i < 2048; i += 512) {
                int r = i >> 4, c = i & 15;
                int gr = rowBase + r;
                int sz = (gr < NPTS) ? 16 : 0;
                int grc = (gr < NPTS) ? gr : (NPTS - 1);
                const size_t gsrc = (size_t)grc * KTOT + (kc + 1) * 128 + c * 8;
                cpa16(sAH + swz(r, c, 256), Ahg + gsrc, sz);
                cpa16(sAL + swz(r, c, 256), Alg + gsrc, sz);
            }
            cpa_wait();
            __syncthreads();
        }
    }

    // ---------------- epilogue ----------------
    const float b3v = (EPI == 1) ? b3[0] : 0.f;
#pragma unroll
    for (int mi = 0; mi < 2; mi++) {
        int lr = warpM + mi * 16 + (t >> 2);
        int gr0 = rowBase + lr, gr8 = gr0 + 8;
        float lp0 = 0.f, lp8 = 0.f;
#pragma unroll
        for (int ni = 0; ni < 4; ni++) {
            int lc = warpN + ni * 8 + (t & 3) * 2;
            float v0 = C[mi][ni][0], v1 = C[mi][ni][1];
            float v2 = C[mi][ni][2], v3 = C[mi][ni][3];
            if (EPI <= 1) {
                float s0 = psc[lc], s1v = psc[lc + 1], d0 = pbi[lc], d1 = pbi[lc + 1];
                v0 = fmaxf(v0 * s0 + d0, 0.f); v1 = fmaxf(v1 * s1v + d1, 0.f);
                v2 = fmaxf(v2 * s0 + d0, 0.f); v3 = fmaxf(v3 * s1v + d1, 0.f);
            }
            if (EPI == 0) {
                __nv_bfloat16 h0, h1, l0, l1;
                if (gr0 < NPTS) {
                    bsplit(v0, h0, l0); bsplit(v1, h1, l1);
                    size_t o = (size_t)gr0 * CH2 + nBase + lc;
                    *(uint32_t*)&g_Hh[o] = pk(h0, h1);
                    *(uint32_t*)&g_Hl[o] = pk(l0, l1);
                }
                if (gr8 < NPTS) {
                    bsplit(v2, h0, l0); bsplit(v3, h1, l1);
                    size_t o = (size_t)gr8 * CH2 + nBase + lc;
                    *(uint32_t*)&g_Hh[o] = pk(h0, h1);
                    *(uint32_t*)&g_Hl[o] = pk(l0, l1);
                }
            } else if (EPI == 1) {
                lp0 += v0 * pw3[lc] + v1 * pw3[lc + 1];
                lp8 += v2 * pw3[lc] + v3 * pw3[lc + 1];
                __nv_bfloat16 h0, h1, l0, l1;
                if (gr0 < NPTS) {
                    size_t o = (size_t)gr0 * CH + lc;
                    *(float2*)&g_h2[o] = make_float2(v0, v1);
                    bsplit(v0, h0, l0); bsplit(v1, h1, l1);
                    *(uint32_t*)&g_h2h[o] = pk(h0, h1);
                    *(uint32_t*)&g_h2l[o] = pk(l0, l1);
                }
                if (gr8 < NPTS) {
                    size_t o = (size_t)gr8 * CH + lc;
                    *(float2*)&g_h2[o] = make_float2(v2, v3);
                    bsplit(v2, h0, l0); bsplit(v3, h1, l1);
                    *(uint32_t*)&g_h2h[o] = pk(h0, h1);
                    *(uint32_t*)&g_h2l[o] = pk(l0, l1);
                }
            } else {
                if (gr0 < NPTS) *(float2*)&g_a[(size_t)gr0 * CH + lc] = make_float2(v0, v1);
                if (gr8 < NPTS) *(float2*)&g_a[(size_t)gr8 * CH + lc] = make_float2(v2, v3);
                unsigned e0 = 0u, e1 = 0u;
                if (gr0 < NPTS) { e0 = encf(v0); e1 = encf(v1); }
                if (gr8 < NPTS) {
                    unsigned f2 = encf(v2), f3 = encf(v3);
                    e0 = (f2 > e0) ? f2 : e0; e1 = (f3 > e1) ? f3 : e1;
                }
                if (e0) atomicMax(&pmax[lc], e0);
                if (e1) atomicMax(&pmax[lc + 1], e1);
            }
        }
        if (EPI == 1) { atomicAdd(&plg[lr], lp0); atomicAdd(&plg[lr + 8], lp8); }
    }
    if (EPI == 1) {
        __syncthreads();
        if (tid < 128 && rowBase + tid < NPTS) out[rowBase + tid] = plg[tid] + b3v;
    }
    if (EPI == 2) {
        __syncthreads();
        if (tid < 128) atomicMax(&g_cmax[tid], pmax[tid]);
    }
}

// ------------------------- sparse mask + attention accumulation --------------
__global__ void mask_accum(const float* __restrict__ xyz,
                           const float* __restrict__ center, const float* __restrict__ normal,
                           const float* __restrict__ pmin, const float* __restrict__ pmax,
                           const float* __restrict__ logit)
{
    __shared__ float4 sn[NPLANES];
    __shared__ float4 sbx[NPLANES];
    __shared__ float scm[CH];
    int tid = threadIdx.x;
    if (tid < NPLANES) {
        float nx = normal[tid * 3], ny = normal[tid * 3 + 1], nz = normal[tid * 3 + 2];
        float off = nx * center[tid * 3] + ny * center[tid * 3 + 1] + nz * center[tid * 3 + 2];
        sn[tid] = make_float4(nx, ny, nz, off);
        sbx[tid] = make_float4(pmin[tid * 3], pmin[tid * 3 + 1], pmax[tid * 3], pmax[tid * 3 + 1]);
    }
    if (tid < CH) scm[tid] = decf(g_cmax[tid]);
    __syncthreads();

    int n = blockIdx.x * blockDim.x + tid;
    unsigned long long m = 0ull;
    int sel = 0;
    if (n < NPTS) {
        float x = xyz[n * 3], y = xyz[n * 3 + 1], z = xyz[n * 3 + 2];
        sel = (logit[n] > 0.0f) ? 1 : 0;
        for (int p = 0; p < NPLANES; p++) {
            float4 nn = sn[p];
            float proj = x * nn.x + y * nn.y + z * nn.z;
            float4 bb = sbx[p];
            bool ok = (fabsf(proj - nn.w) < 0.1f) &&
                      (x >= bb.x) && (x < bb.z) && (y >= bb.y) && (y < bb.w);
            if (ok) m |= (1ull << p);
        }
    }

    int lane = tid & 31;
    for (;;) {
        unsigned act = __ballot_sync(0xffffffffu, m != 0ull);
        if (!act) break;
        int src = __ffs(act) - 1;
        unsigned long long ms = __shfl_sync(0xffffffffu, m, src);
        int ns  = __shfl_sync(0xffffffffu, n, src);
        int sls = __shfl_sync(0xffffffffu, sel, src);
        int p = __ffsll((long long)ms) - 1;
        if (lane == src) m &= (m - 1);

        float* num = g_num + ((sls ? 0 : 1) * NPLANES + p) * CH;
        float* den = g_den + ((sls ? 0 : 1) * NPLANES + p) * CH;
        const float* ar = g_a  + (size_t)ns * CH;
        const float* hr = g_h2 + (size_t)ns * CH;
#pragma unroll
        for (int i = 0; i < 4; i++) {
            int c = lane + 32 * i;
            float e = expf(ar[c] - scm[c]);
            atomicAdd(&num[c], e * hr[c]);
            atomicAdd(&den[c], e);
        }
    }
}

// ------------------------- finalize ------------------------------------------
__global__ void finalize_kernel(const float* __restrict__ Wm, const float* __restrict__ bm,
                                const float* __restrict__ center, const float* __restrict__ normal,
                                const float* __restrict__ pmin, const float* __restrict__ pmax,
                                float* __restrict__ out)
{
    int bp = blockIdx.x;
    int pool = bp >> 6, p = bp & 63;
    __shared__ float agg[CH];
    int j = threadIdx.x;
    int base = (pool * NPLANES + p) * CH;
    agg[j] = g_num[base + j] / (g_den[base + j] + 1e-9f);
    __syncthreads();

    float s = __ldg(&bm[j]);
#pragma unroll 8
    for (int c = 0; c < CH; c++) s += agg[c] * __ldg(&Wm[c * CH + j]);
    s = fmaxf(s, 0.f);

    float* ob = out + NPTS + (size_t)pool * NPLANES * FEAT_OUT + p * FEAT_OUT;
    ob[j] = s;
    if (j < 12) {
        float v;
        if (j < 3)      v = center[p * 3 + j];
        else if (j < 6) v = normal[p * 3 + (j - 3)];
        else if (j < 9) v = pmin[p * 3 + (j - 6)];
        else            v = pmax[p * 3 + (j - 9)];
        ob[CH + j] = v;
    }
}

// ------------------------- launch --------------------------------------------
extern "C" void kernel_launch(void* const* d_in, const int* in_sizes, int n_in,
                              void* d_out, int out_size)
{
    const float* feature = (const float*)d_in[0];
    const float* xyz     = (const float*)d_in[1];
    const float* center  = (const float*)d_in[2];
    const float* normal  = (const float*)d_in[3];
    const float* pmin    = (const float*)d_in[4];
    const float* pmax    = (const float*)d_in[5];
    const float* W1      = (const float*)d_in[6];
    const float* s1      = (const float*)d_in[7];
    const float* b1      = (const float*)d_in[8];
    const float* W2      = (const float*)d_in[9];
    const float* s2      = (const float*)d_in[10];
    const float* b2      = (const float*)d_in[11];
    const float* W3      = (const float*)d_in[12];
    const float* b3      = (const float*)d_in[13];
    const float* Wa      = (const float*)d_in[14];
    const float* Wm      = (const float*)d_in[15];
    const float* bm      = (const float*)d_in[16];
    float* out = (float*)d_out;

    __nv_bfloat16 *Hh, *Hl, *h2h, *h2l, *W1h, *W1l, *W2h, *W2l, *Wah, *Wal;
    cudaGetSymbolAddress((void**)&Hh,  g_Hh);
    cudaGetSymbolAddress((void**)&Hl,  g_Hl);
    cudaGetSymbolAddress((void**)&h2h, g_h2h);
    cudaGetSymbolAddress((void**)&h2l, g_h2l);
    cudaGetSymbolAddress((void**)&W1h, g_W1h);
    cudaGetSymbolAddress((void**)&W1l, g_W1l);
    cudaGetSymbolAddress((void**)&W2h, g_W2h);
    cudaGetSymbolAddress((void**)&W2l, g_W2l);
    cudaGetSymbolAddress((void**)&Wah, g_Wah);
    cudaGetSymbolAddress((void**)&Wal, g_Wal);

    // smem totals: fc1/att: 2*32K(B) + 2*32K(A) + 2K = 133120 ; fc2: 2*64K + 2*32K + 2K = 198656
    const int SM_SM = 133120, SM_LG = 198656;
    cudaFuncSetAttribute(gemm_mma<128, 0, 0>, cudaFuncAttributeMaxDynamicSharedMemorySize, SM_SM);
    cudaFuncSetAttribute(gemm_mma<256, 1, 1>, cudaFuncAttributeMaxDynamicSharedMemorySize, SM_LG);
    cudaFuncSetAttribute(gemm_mma<128, 1, 2>, cudaFuncAttributeMaxDynamicSharedMemorySize, SM_SM);

    const int MB = (NPTS + 127) / 128;   // 782

    init_kernel<<<64, 256>>>();
    prep_kernel<<<320, 256>>>(W1, W2, Wa);
    gemm_mma<128, 0, 0><<<dim3(MB, 2), 512, SM_SM>>>(
        feature, nullptr, nullptr, W1h, W1l, s1, b1, nullptr, nullptr, nullptr);
    gemm_mma<256, 1, 1><<<dim3(MB, 1), 512, SM_LG>>>(
        nullptr, Hh, Hl, W2h, W2l, s2, b2, W3, b3, out);
    gemm_mma<128, 1, 2><<<dim3(MB, 1), 512, SM_SM>>>(
        nullptr, h2h, h2l, Wah, Wal, nullptr, nullptr, nullptr, nullptr, nullptr);
    mask_accum<<<(NPTS + 255) / 256, 256>>>(xyz, center, normal, pmin, pmax, out);
    finalize_kernel<<<128, 128>>>(Wm, bm, center, normal, pmin, pmax, out);
}

// round 14
// speedup vs baseline: 1.8041x; 1.2886x over previous
#include <cuda_runtime.h>
#include <cuda_bf16.h>
#include <math.h>
#include <stdint.h>

#define NPTS 100000
#define CH 128
#define CH2 256
#define NPLANES 64
#define FEAT_OUT 140

// ------------------------- scratch (__device__ globals) ----------------------
__device__ float g_h2[(size_t)NPTS * CH];    // fc2 out fp32 (mask_accum)
__device__ float g_a [(size_t)NPTS * CH];    // attention activations
__device__ float g_num[2 * NPLANES * CH];
__device__ float g_den[2 * NPLANES * CH];
__device__ unsigned g_cmax[CH];

// pre-split weights, [n][k] layout (bf16 hi/lo)
__device__ __nv_bfloat16 g_W1h[CH2 * CH], g_W1l[CH2 * CH];   // n=256, k=128
__device__ __nv_bfloat16 g_W2h[CH * CH2], g_W2l[CH * CH2];   // n=128, k=256
__device__ __nv_bfloat16 g_Wah[CH * CH],  g_Wal[CH * CH];    // n=128, k=128

__device__ __forceinline__ unsigned encf(float f) {
    unsigned u = __float_as_uint(f);
    return (u & 0x80000000u) ? ~u : (u | 0x80000000u);
}
__device__ __forceinline__ float decf(unsigned u) {
    return __uint_as_float((u & 0x80000000u) ? (u & 0x7fffffffu) : ~u);
}
__device__ __forceinline__ uint32_t pk(__nv_bfloat16 a, __nv_bfloat16 b) {
    return ((uint32_t)__bfloat16_as_ushort(b) << 16) | (uint32_t)__bfloat16_as_ushort(a);
}
__device__ __forceinline__ void bsplit(float f, __nv_bfloat16& h, __nv_bfloat16& l) {
    h = __float2bfloat16(f);
    l = __float2bfloat16(f - __bfloat162float(h));
}

// ---------------- prep: weight split + accumulator init ----------------------
__global__ void prep_kernel(const float* __restrict__ W1, const float* __restrict__ W2,
                            const float* __restrict__ Wa)
{
    int t = blockIdx.x * blockDim.x + threadIdx.x;
    if (t < 2 * NPLANES * CH) { g_num[t] = 0.f; g_den[t] = 0.f; }
    if (t < CH) g_cmax[t] = encf(-3.0e38f);
    __nv_bfloat16 h, l;
    if (t < 32768) {
        int n = t >> 7, k = t & 127;
        bsplit(W1[k * CH2 + n], h, l);
        g_W1h[t] = h; g_W1l[t] = l;
    } else if (t < 65536) {
        int u = t - 32768;
        int n = u >> 8, k = u & 255;
        bsplit(W2[k * CH + n], h, l);
        g_W2h[u] = h; g_W2l[u] = l;
    } else if (t < 81920) {
        int u = t - 65536;
        int n = u >> 7, k = u & 127;
        bsplit(Wa[k * CH + n], h, l);
        g_Wah[u] = h; g_Wal[u] = l;
    }
}

// ------------------------- primitives ----------------------------------------
__device__ __forceinline__ void hmma(float* c, const uint32_t* a,
                                     uint32_t b0, uint32_t b1) {
    asm("mma.sync.aligned.m16n8k16.row.col.f32.bf16.bf16.f32 "
        "{%0,%1,%2,%3},{%4,%5,%6,%7},{%8,%9},{%0,%1,%2,%3};"
        : "+f"(c[0]), "+f"(c[1]), "+f"(c[2]), "+f"(c[3])
        : "r"(a[0]), "r"(a[1]), "r"(a[2]), "r"(a[3]), "r"(b0), "r"(b1));
}
__device__ __forceinline__ void ldsm4(uint32_t* r, uint32_t saddr) {
    asm volatile("ldmatrix.sync.aligned.m8n8.x4.shared.b16 {%0,%1,%2,%3}, [%4];"
                 : "=r"(r[0]), "=r"(r[1]), "=r"(r[2]), "=r"(r[3]) : "r"(saddr));
}
__device__ __forceinline__ void cpa16(uint32_t dst, const void* src) {
    asm volatile("cp.async.cg.shared.global [%0], [%1], 16;"
                 :: "r"(dst), "l"(src) : "memory");
}
__device__ __forceinline__ void cpa_wait() {
    asm volatile("cp.async.commit_group;\n\tcp.async.wait_group 0;" ::: "memory");
}
// XOR swizzle for 16B chunk c within a 256B row — conflict-free for ldmatrix
__device__ __forceinline__ uint32_t swz(int row, int c) {
    return (uint32_t)(row * 256 + ((c ^ (row & 7)) << 4));
}
__device__ __forceinline__ void sts32(uint32_t addr, uint32_t v) {
    asm volatile("st.shared.b32 [%0], %1;" :: "r"(addr), "r"(v));
}

// SMEM layout (byte offsets into dynamic smem; all operand mats 128x128 bf16)
#define OFF_AH 0
#define OFF_AL 32768
#define OFF_BH 65536
#define OFF_BL 98304
#define OFF_CH 131072
#define OFF_CL 163840
#define OFF_PAR 196608
#define SMEM_TOT 204800

// stage a 128x128 bf16 hi/lo weight chunk -> B buffers (cp.async)
__device__ __forceinline__ void stage_w(uint32_t sH, uint32_t sL,
                                        const __nv_bfloat16* __restrict__ Wh,
                                        const __nv_bfloat16* __restrict__ Wl,
                                        int ldk, int nOff, int kOff, int tid)
{
#pragma unroll
    for (int i = tid; i < 2048; i += 512) {
        int n = i >> 4, c = i & 15;
        size_t gidx = (size_t)(nOff + n) * ldk + kOff + c * 8;
        cpa16(sH + swz(n, c), Wh + gidx);
        cpa16(sL + swz(n, c), Wl + gidx);
    }
}

// one 128-K MMA pass: 8 k-steps x (8 ldsm4 + 24 HMMA), accumulate into C
__device__ __forceinline__ void mma_phase(float C[2][4][4],
        uint32_t sAH, uint32_t sAL, uint32_t sBH, uint32_t sBL,
        int rA0, int cgA, int rB0, int cgB)
{
#pragma unroll
    for (int s = 0; s < 8; s++) {
        uint32_t Ah[2][4], Al[2][4], Bh[2][4], Bl[2][4];
#pragma unroll
        for (int mi = 0; mi < 2; mi++) {
            uint32_t o = swz(rA0 + mi * 16, 2 * s + cgA);
            ldsm4(Ah[mi], sAH + o);
            ldsm4(Al[mi], sAL + o);
        }
#pragma unroll
        for (int nb = 0; nb < 2; nb++) {
            uint32_t o = swz(rB0 + nb * 16, 2 * s + cgB);
            ldsm4(Bh[nb], sBH + o);
            ldsm4(Bl[nb], sBL + o);
        }
#pragma unroll
        for (int mi = 0; mi < 2; mi++)
#pragma unroll
            for (int ni = 0; ni < 4; ni++)
                hmma(C[mi][ni], Ah[mi], Bh[ni >> 1][(ni & 1) * 2], Bh[ni >> 1][(ni & 1) * 2 + 1]);
#pragma unroll
        for (int mi = 0; mi < 2; mi++)
#pragma unroll
            for (int ni = 0; ni < 4; ni++)
                hmma(C[mi][ni], Ah[mi], Bl[ni >> 1][(ni & 1) * 2], Bl[ni >> 1][(ni & 1) * 2 + 1]);
#pragma unroll
        for (int mi = 0; mi < 2; mi++)
#pragma unroll
            for (int ni = 0; ni < 4; ni++)
                hmma(C[mi][ni], Al[mi], Bh[ni >> 1][(ni & 1) * 2], Bh[ni >> 1][(ni & 1) * 2 + 1]);
    }
}

#define ZERO_C(C) do { \
    _Pragma("unroll") for (int mi = 0; mi < 2; mi++) \
    _Pragma("unroll") for (int ni = 0; ni < 4; ni++) \
    _Pragma("unroll") for (int q = 0; q < 4; q++) (C)[mi][ni][q] = 0.f; } while (0)

// split-store a scaled pair into hi/lo SMEM matrices at (row, col lc..lc+1)
__device__ __forceinline__ void st_split(uint32_t sH, uint32_t sL, int row, int lc,
                                         float v0, float v1) {
    __nv_bfloat16 h0, l0, h1, l1;
    bsplit(v0, h0, l0); bsplit(v1, h1, l1);
    uint32_t o = swz(row, lc >> 3) + ((lc << 1) & 15);
    sts32(sH + o, pk(h0, h1));
    sts32(sL + o, pk(l0, l1));
}

// ============================================================================
// fused fc1 -> fc2(+fc3 logit) -> att : one CTA per 128-row tile
// ============================================================================
__global__ __launch_bounds__(512, 1)
void fused_gemm(const float* __restrict__ F,
                const float* __restrict__ s1, const float* __restrict__ b1,
                const float* __restrict__ s2, const float* __restrict__ b2,
                const float* __restrict__ W3, const float* __restrict__ b3,
                float* __restrict__ out)
{
    extern __shared__ __align__(16) char smx[];
    const uint32_t sb = (uint32_t)__cvta_generic_to_shared(smx);
    const uint32_t sAH = sb + OFF_AH, sAL = sb + OFF_AL;
    const uint32_t sBH = sb + OFF_BH, sBL = sb + OFF_BL;
    const uint32_t sCH = sb + OFF_CH, sCL = sb + OFF_CL;
    float* par = (float*)(smx + OFF_PAR);
    float *sc0 = par,       *bi0 = par + 128, *sc1 = par + 256, *bi1 = par + 384;
    float *ps2 = par + 512, *pb2 = par + 640, *pw3 = par + 768, *plg = par + 896;
    unsigned* pmax = (unsigned*)(par + 1024);

    const int tid = threadIdx.x, wid = tid >> 5, t = tid & 31;
    const int rowBase = blockIdx.x * 128;
    const int warpM = (wid & 3) * 32, warpN = (wid >> 2) * 32;
    const int g = t >> 3;
    const int rA0 = warpM + (g & 1) * 8 + (t & 7), cgA = g >> 1;
    const int rB0 = warpN + (g >> 1) * 8 + (t & 7), cgB = g & 1;

    if (tid < 128) {
        sc0[tid] = s1[tid];        bi0[tid] = b1[tid];
        sc1[tid] = s1[128 + tid];  bi1[tid] = b1[128 + tid];
        ps2[tid] = s2[tid];        pb2[tid] = b2[tid];
        pw3[tid] = W3[tid];        plg[tid] = 0.f;  pmax[tid] = 0u;
    }

    // ---- stage W1 half0 -> B ; convert F -> A (hi/lo, swizzled)
    stage_w(sBH, sBL, g_W1h, g_W1l, 128, 0, 0, tid);
    {
        const float4 z4 = make_float4(0.f, 0.f, 0.f, 0.f);
        for (int i = tid; i < 4096; i += 512) {
            int r = i >> 5, c4 = i & 31;
            int gr = rowBase + r;
            float4 v = (gr < NPTS) ? *(const float4*)&F[(size_t)gr * CH + c4 * 4] : z4;
            __nv_bfloat16 h0, h1, h2v, h3, l0, l1, l2, l3;
            bsplit(v.x, h0, l0); bsplit(v.y, h1, l1);
            bsplit(v.z, h2v, l2); bsplit(v.w, h3, l3);
            uint32_t off = swz(r, c4 >> 1) + (c4 & 1) * 8;
            *(uint2*)(smx + OFF_AH + off) = make_uint2(pk(h0, h1), pk(h2v, h3));
            *(uint2*)(smx + OFF_AL + off) = make_uint2(pk(l0, l1), pk(l2, l3));
        }
    }
    cpa_wait();
    __syncthreads();

    float Cr[2][4][4];

    // ================= GEMM1 half 0: Hsm0 = relu((F@W1[:,0:128])*s+b) -> Cbuf
    ZERO_C(Cr);
    mma_phase(Cr, sAH, sAL, sBH, sBL, rA0, cgA, rB0, cgB);
    __syncthreads();                      // B free; A still holds F
    stage_w(sBH, sBL, g_W1h, g_W1l, 128, 128, 0, tid);   // W1 half1 (overlaps epi)
#pragma unroll
    for (int mi = 0; mi < 2; mi++) {
        int lr = warpM + mi * 16 + (t >> 2);
#pragma unroll
        for (int ni = 0; ni < 4; ni++) {
            int lc = warpN + ni * 8 + (t & 3) * 2;
            float s0v = sc0[lc], s1v = sc0[lc + 1], d0 = bi0[lc], d1 = bi0[lc + 1];
            st_split(sCH, sCL, lr,     lc, fmaxf(Cr[mi][ni][0] * s0v + d0, 0.f),
                                           fmaxf(Cr[mi][ni][1] * s1v + d1, 0.f));
            st_split(sCH, sCL, lr + 8, lc, fmaxf(Cr[mi][ni][2] * s0v + d0, 0.f),
                                           fmaxf(Cr[mi][ni][3] * s1v + d1, 0.f));
        }
    }
    cpa_wait();
    __syncthreads();

    // ================= GEMM1 half 1: Hsm1 -> Abuf (overwrites F)
    ZERO_C(Cr);
    mma_phase(Cr, sAH, sAL, sBH, sBL, rA0, cgA, rB0, cgB);
    __syncthreads();                      // A and B free
    stage_w(sBH, sBL, g_W2h, g_W2l, 256, 0, 0, tid);     // W2 k-chunk 0 (overlaps epi)
#pragma unroll
    for (int mi = 0; mi < 2; mi++) {
        int lr = warpM + mi * 16 + (t >> 2);
#pragma unroll
        for (int ni = 0; ni < 4; ni++) {
            int lc = warpN + ni * 8 + (t & 3) * 2;
            float s0v = sc1[lc], s1v = sc1[lc + 1], d0 = bi1[lc], d1 = bi1[lc + 1];
            st_split(sAH, sAL, lr,     lc, fmaxf(Cr[mi][ni][0] * s0v + d0, 0.f),
                                           fmaxf(Cr[mi][ni][1] * s1v + d1, 0.f));
            st_split(sAH, sAL, lr + 8, lc, fmaxf(Cr[mi][ni][2] * s0v + d0, 0.f),
                                           fmaxf(Cr[mi][ni][3] * s1v + d1, 0.f));
        }
    }
    cpa_wait();
    __syncthreads();

    // ================= GEMM2: h2 = relu((H@W2)*s2+b2), K=256 over C then A
    ZERO_C(Cr);
    mma_phase(Cr, sCH, sCL, sBH, sBL, rA0, cgA, rB0, cgB);    // k 0..127 (Hsm0)
    __syncthreads();                      // B free
    stage_w(sBH, sBL, g_W2h, g_W2l, 256, 0, 128, tid);   // W2 k-chunk 1
    cpa_wait();
    __syncthreads();
    mma_phase(Cr, sAH, sAL, sBH, sBL, rA0, cgA, rB0, cgB);    // k 128..255 (Hsm1)
    __syncthreads();                      // A, B, C free
    stage_w(sBH, sBL, g_Wah, g_Wal, 128, 0, 0, tid);     // Wa (overlaps epi)

    // epilogue fc2: h2 fp32 -> gmem, split -> Cbuf, fused fc3 logit
#pragma unroll
    for (int mi = 0; mi < 2; mi++) {
        int lr = warpM + mi * 16 + (t >> 2);
        int gr0 = rowBase + lr, gr8 = gr0 + 8;
        float lp0 = 0.f, lp8 = 0.f;
#pragma unroll
        for (int ni = 0; ni < 4; ni++) {
            int lc = warpN + ni * 8 + (t & 3) * 2;
            float s0v = ps2[lc], s1v = ps2[lc + 1], d0 = pb2[lc], d1 = pb2[lc + 1];
            float v0 = fmaxf(Cr[mi][ni][0] * s0v + d0, 0.f);
            float v1 = fmaxf(Cr[mi][ni][1] * s1v + d1, 0.f);
            float v2 = fmaxf(Cr[mi][ni][2] * s0v + d0, 0.f);
            float v3 = fmaxf(Cr[mi][ni][3] * s1v + d1, 0.f);
            lp0 += v0 * pw3[lc] + v1 * pw3[lc + 1];
            lp8 += v2 * pw3[lc] + v3 * pw3[lc + 1];
            st_split(sCH, sCL, lr,     lc, v0, v1);
            st_split(sCH, sCL, lr + 8, lc, v2, v3);
            if (gr0 < NPTS) *(float2*)&g_h2[(size_t)gr0 * CH + lc] = make_float2(v0, v1);
            if (gr8 < NPTS) *(float2*)&g_h2[(size_t)gr8 * CH + lc] = make_float2(v2, v3);
        }
        atomicAdd(&plg[lr], lp0);
        atomicAdd(&plg[lr + 8], lp8);
    }
    cpa_wait();
    __syncthreads();
    if (tid < 128 && rowBase + tid < NPTS) out[rowBase + tid] = plg[tid] + b3[0];

    // ================= GEMM3: a = h2 @ Wa (raw) + colmax
    ZERO_C(Cr);
    mma_phase(Cr, sCH, sCL, sBH, sBL, rA0, cgA, rB0, cgB);
#pragma unroll
    for (int mi = 0; mi < 2; mi++) {
        int lr = warpM + mi * 16 + (t >> 2);
        int gr0 = rowBase + lr, gr8 = gr0 + 8;
#pragma unroll
        for (int ni = 0; ni < 4; ni++) {
            int lc = warpN + ni * 8 + (t & 3) * 2;
            float v0 = Cr[mi][ni][0], v1 = Cr[mi][ni][1];
            float v2 = Cr[mi][ni][2], v3 = Cr[mi][ni][3];
            if (gr0 < NPTS) *(float2*)&g_a[(size_t)gr0 * CH + lc] = make_float2(v0, v1);
            if (gr8 < NPTS) *(float2*)&g_a[(size_t)gr8 * CH + lc] = make_float2(v2, v3);
            unsigned e0 = 0u, e1 = 0u;
            if (gr0 < NPTS) { e0 = encf(v0); e1 = encf(v1); }
            if (gr8 < NPTS) {
                unsigned f2 = encf(v2), f3 = encf(v3);
                e0 = (f2 > e0) ? f2 : e0; e1 = (f3 > e1) ? f3 : e1;
            }
            if (e0) atomicMax(&pmax[lc], e0);
            if (e1) atomicMax(&pmax[lc + 1], e1);
        }
    }
    __syncthreads();
    if (tid < 128) atomicMax(&g_cmax[tid], pmax[tid]);
}

// ------------------------- sparse mask + attention accumulation --------------
__global__ void mask_accum(const float* __restrict__ xyz,
                           const float* __restrict__ center, const float* __restrict__ normal,
                           const float* __restrict__ pmin, const float* __restrict__ pmax,
                           const float* __restrict__ logit)
{
    __shared__ float4 sn[NPLANES];
    __shared__ float4 sbx[NPLANES];
    __shared__ float scm[CH];
    int tid = threadIdx.x;
    if (tid < NPLANES) {
        float nx = normal[tid * 3], ny = normal[tid * 3 + 1], nz = normal[tid * 3 + 2];
        float off = nx * center[tid * 3] + ny * center[tid * 3 + 1] + nz * center[tid * 3 + 2];
        sn[tid] = make_float4(nx, ny, nz, off);
        sbx[tid] = make_float4(pmin[tid * 3], pmin[tid * 3 + 1], pmax[tid * 3], pmax[tid * 3 + 1]);
    }
    if (tid < CH) scm[tid] = decf(g_cmax[tid]);
    __syncthreads();

    int n = blockIdx.x * blockDim.x + tid;
    unsigned long long m = 0ull;
    int sel = 0;
    if (n < NPTS) {
        float x = xyz[n * 3], y = xyz[n * 3 + 1], z = xyz[n * 3 + 2];
        sel = (logit[n] > 0.0f) ? 1 : 0;
        for (int p = 0; p < NPLANES; p++) {
            float4 nn = sn[p];
            float proj = x * nn.x + y * nn.y + z * nn.z;
            float4 bb = sbx[p];
            bool ok = (fabsf(proj - nn.w) < 0.1f) &&
                      (x >= bb.x) && (x < bb.z) && (y >= bb.y) && (y < bb.w);
            if (ok) m |= (1ull << p);
        }
    }

    int lane = tid & 31;
    for (;;) {
        unsigned act = __ballot_sync(0xffffffffu, m != 0ull);
        if (!act) break;
        int src = __ffs(act) - 1;
        unsigned long long ms = __shfl_sync(0xffffffffu, m, src);
        int ns  = __shfl_sync(0xffffffffu, n, src);
        int sls = __shfl_sync(0xffffffffu, sel, src);
        int p = __ffsll((long long)ms) - 1;
        if (lane == src) m &= (m - 1);

        float* num = g_num + ((sls ? 0 : 1) * NPLANES + p) * CH;
        float* den = g_den + ((sls ? 0 : 1) * NPLANES + p) * CH;
        const float* ar = g_a  + (size_t)ns * CH;
        const float* hr = g_h2 + (size_t)ns * CH;
#pragma unroll
        for (int i = 0; i < 4; i++) {
            int c = lane + 32 * i;
            float e = expf(ar[c] - scm[c]);
            atomicAdd(&num[c], e * hr[c]);
            atomicAdd(&den[c], e);
        }
    }
}

// ------------------------- finalize ------------------------------------------
__global__ void finalize_kernel(const float* __restrict__ Wm, const float* __restrict__ bm,
                                const float* __restrict__ center, const float* __restrict__ normal,
                                const float* __restrict__ pmin, const float* __restrict__ pmax,
                                float* __restrict__ out)
{
    int bp = blockIdx.x;
    int pool = bp >> 6, p = bp & 63;
    __shared__ float agg[CH];
    int j = threadIdx.x;
    int base = (pool * NPLANES + p) * CH;
    agg[j] = g_num[base + j] / (g_den[base + j] + 1e-9f);
    __syncthreads();

    float s = __ldg(&bm[j]);
#pragma unroll 8
    for (int c = 0; c < CH; c++) s += agg[c] * __ldg(&Wm[c * CH + j]);
    s = fmaxf(s, 0.f);

    float* ob = out + NPTS + (size_t)pool * NPLANES * FEAT_OUT + p * FEAT_OUT;
    ob[j] = s;
    if (j < 12) {
        float v;
        if (j < 3)      v = center[p * 3 + j];
        else if (j < 6) v = normal[p * 3 + (j - 3)];
        else if (j < 9) v = pmin[p * 3 + (j - 6)];
        else            v = pmax[p * 3 + (j - 9)];
        ob[CH + j] = v;
    }
}

// ------------------------- launch --------------------------------------------
extern "C" void kernel_launch(void* const* d_in, const int* in_sizes, int n_in,
                              void* d_out, int out_size)
{
    const float* feature = (const float*)d_in[0];
    const float* xyz     = (const float*)d_in[1];
    const float* center  = (const float*)d_in[2];
    const float* normal  = (const float*)d_in[3];
    const float* pmin    = (const float*)d_in[4];
    const float* pmax    = (const float*)d_in[5];
    const float* W1      = (const float*)d_in[6];
    const float* s1      = (const float*)d_in[7];
    const float* b1      = (const float*)d_in[8];
    const float* W2      = (const float*)d_in[9];
    const float* s2      = (const float*)d_in[10];
    const float* b2      = (const float*)d_in[11];
    const float* W3      = (const float*)d_in[12];
    const float* b3      = (const float*)d_in[13];
    const float* Wa      = (const float*)d_in[14];
    const float* Wm      = (const float*)d_in[15];
    const float* bm      = (const float*)d_in[16];
    float* out = (float*)d_out;

    cudaFuncSetAttribute(fused_gemm, cudaFuncAttributeMaxDynamicSharedMemorySize, SMEM_TOT);

    const int MB = (NPTS + 127) / 128;   // 782

    prep_kernel<<<320, 256>>>(W1, W2, Wa);
    fused_gemm<<<MB, 512, SMEM_TOT>>>(feature, s1, b1, s2, b2, W3, b3, out);
    mask_accum<<<(NPTS + 255) / 256, 256>>>(xyz, center, normal, pmin, pmax, out);
    finalize_kernel<<<128, 128>>>(Wm, bm, center, normal, pmin, pmax, out);
}

// round 16
// speedup vs baseline: 2.1086x; 1.1688x over previous
#include <cuda_runtime.h>
#include <cuda_bf16.h>
#include <math.h>
#include <stdint.h>

#define NPTS 100000
#define CH 128
#define CH2 256
#define NPLANES 64
#define FEAT_OUT 140

// ------------------------- scratch (__device__ globals) ----------------------
__device__ float g_h2[(size_t)NPTS * CH];    // fc2 out fp32 (masked rows only)
__device__ float g_a [(size_t)NPTS * CH];    // attention activations (masked rows only)
__device__ float g_num[2 * NPLANES * CH];
__device__ float g_den[2 * NPLANES * CH];
__device__ unsigned g_cmax[CH];

// pre-split weights, [n][k] layout (bf16 hi/lo)
__device__ __nv_bfloat16 g_W1h[CH2 * CH], g_W1l[CH2 * CH];   // n=256, k=128
__device__ __nv_bfloat16 g_W2h[CH * CH2], g_W2l[CH * CH2];   // n=128, k=256
__device__ __nv_bfloat16 g_Wah[CH * CH],  g_Wal[CH * CH];    // n=128, k=128

__device__ __forceinline__ unsigned encf(float f) {
    unsigned u = __float_as_uint(f);
    return (u & 0x80000000u) ? ~u : (u | 0x80000000u);
}
__device__ __forceinline__ float decf(unsigned u) {
    return __uint_as_float((u & 0x80000000u) ? (u & 0x7fffffffu) : ~u);
}
__device__ __forceinline__ uint32_t pk(__nv_bfloat16 a, __nv_bfloat16 b) {
    return ((uint32_t)__bfloat16_as_ushort(b) << 16) | (uint32_t)__bfloat16_as_ushort(a);
}
__device__ __forceinline__ void bsplit(float f, __nv_bfloat16& h, __nv_bfloat16& l) {
    h = __float2bfloat16(f);
    l = __float2bfloat16(f - __bfloat162float(h));
}

// ---------------- prep: weight split + accumulator init ----------------------
__global__ void prep_kernel(const float* __restrict__ W1, const float* __restrict__ W2,
                            const float* __restrict__ Wa)
{
    int t = blockIdx.x * blockDim.x + threadIdx.x;
    if (t < 2 * NPLANES * CH) { g_num[t] = 0.f; g_den[t] = 0.f; }
    if (t < CH) g_cmax[t] = encf(-3.0e38f);
    __nv_bfloat16 h, l;
    if (t < 32768) {
        int n = t >> 7, k = t & 127;
        bsplit(W1[k * CH2 + n], h, l);
        g_W1h[t] = h; g_W1l[t] = l;
    } else if (t < 65536) {
        int u = t - 32768;
        int n = u >> 8, k = u & 255;
        bsplit(W2[k * CH + n], h, l);
        g_W2h[u] = h; g_W2l[u] = l;
    } else if (t < 81920) {
        int u = t - 65536;
        int n = u >> 7, k = u & 127;
        bsplit(Wa[k * CH + n], h, l);
        g_Wah[u] = h; g_Wal[u] = l;
    }
}

// ------------------------- primitives ----------------------------------------
__device__ __forceinline__ void hmma(float* c, const uint32_t* a,
                                     uint32_t b0, uint32_t b1) {
    asm("mma.sync.aligned.m16n8k16.row.col.f32.bf16.bf16.f32 "
        "{%0,%1,%2,%3},{%4,%5,%6,%7},{%8,%9},{%0,%1,%2,%3};"
        : "+f"(c[0]), "+f"(c[1]), "+f"(c[2]), "+f"(c[3])
        : "r"(a[0]), "r"(a[1]), "r"(a[2]), "r"(a[3]), "r"(b0), "r"(b1));
}
__device__ __forceinline__ void ldsm4(uint32_t* r, uint32_t saddr) {
    asm volatile("ldmatrix.sync.aligned.m8n8.x4.shared.b16 {%0,%1,%2,%3}, [%4];"
                 : "=r"(r[0]), "=r"(r[1]), "=r"(r[2]), "=r"(r[3]) : "r"(saddr));
}
__device__ __forceinline__ void cpa16(uint32_t dst, const void* src) {
    asm volatile("cp.async.cg.shared.global [%0], [%1], 16;"
                 :: "r"(dst), "l"(src) : "memory");
}
__device__ __forceinline__ void cpa_wait() {
    asm volatile("cp.async.commit_group;\n\tcp.async.wait_group 0;" ::: "memory");
}
// XOR swizzle for 16B chunk c within a 256B row — conflict-free for ldmatrix
__device__ __forceinline__ uint32_t swz(int row, int c) {
    return (uint32_t)(row * 256 + ((c ^ (row & 7)) << 4));
}
__device__ __forceinline__ void sts32(uint32_t addr, uint32_t v) {
    asm volatile("st.shared.b32 [%0], %1;" :: "r"(addr), "r"(v));
}

// SMEM layout (byte offsets into dynamic smem; all operand mats 128x128 bf16)
#define OFF_AH 0
#define OFF_AL 32768
#define OFF_BH 65536
#define OFF_BL 98304
#define OFF_CH 131072
#define OFF_CL 163840
#define OFF_PAR 196608
#define SMEM_TOT 204800

// stage a 128x128 bf16 hi/lo weight chunk -> B buffers (cp.async)
__device__ __forceinline__ void stage_w(uint32_t sH, uint32_t sL,
                                        const __nv_bfloat16* __restrict__ Wh,
                                        const __nv_bfloat16* __restrict__ Wl,
                                        int ldk, int nOff, int kOff, int tid)
{
#pragma unroll
    for (int i = tid; i < 2048; i += 512) {
        int n = i >> 4, c = i & 15;
        size_t gidx = (size_t)(nOff + n) * ldk + kOff + c * 8;
        cpa16(sH + swz(n, c), Wh + gidx);
        cpa16(sL + swz(n, c), Wl + gidx);
    }
}

// one 128-K MMA pass: 8 k-steps x (8 ldsm4 + 24 HMMA), accumulate into C
__device__ __forceinline__ void mma_phase(float C[2][4][4],
        uint32_t sAH, uint32_t sAL, uint32_t sBH, uint32_t sBL,
        int rA0, int cgA, int rB0, int cgB)
{
#pragma unroll
    for (int s = 0; s < 8; s++) {
        uint32_t Ah[2][4], Al[2][4], Bh[2][4], Bl[2][4];
#pragma unroll
        for (int mi = 0; mi < 2; mi++) {
            uint32_t o = swz(rA0 + mi * 16, 2 * s + cgA);
            ldsm4(Ah[mi], sAH + o);
            ldsm4(Al[mi], sAL + o);
        }
#pragma unroll
        for (int nb = 0; nb < 2; nb++) {
            uint32_t o = swz(rB0 + nb * 16, 2 * s + cgB);
            ldsm4(Bh[nb], sBH + o);
            ldsm4(Bl[nb], sBL + o);
        }
#pragma unroll
        for (int mi = 0; mi < 2; mi++)
#pragma unroll
            for (int ni = 0; ni < 4; ni++)
                hmma(C[mi][ni], Ah[mi], Bh[ni >> 1][(ni & 1) * 2], Bh[ni >> 1][(ni & 1) * 2 + 1]);
#pragma unroll
        for (int mi = 0; mi < 2; mi++)
#pragma unroll
            for (int ni = 0; ni < 4; ni++)
                hmma(C[mi][ni], Ah[mi], Bl[ni >> 1][(ni & 1) * 2], Bl[ni >> 1][(ni & 1) * 2 + 1]);
#pragma unroll
        for (int mi = 0; mi < 2; mi++)
#pragma unroll
            for (int ni = 0; ni < 4; ni++)
                hmma(C[mi][ni], Al[mi], Bh[ni >> 1][(ni & 1) * 2], Bh[ni >> 1][(ni & 1) * 2 + 1]);
    }
}

#define ZERO_C(C) do { \
    _Pragma("unroll") for (int mi = 0; mi < 2; mi++) \
    _Pragma("unroll") for (int ni = 0; ni < 4; ni++) \
    _Pragma("unroll") for (int q = 0; q < 4; q++) (C)[mi][ni][q] = 0.f; } while (0)

// split-store a scaled pair into hi/lo SMEM matrices at (row, col lc..lc+1)
__device__ __forceinline__ void st_split(uint32_t sH, uint32_t sL, int row, int lc,
                                         float v0, float v1) {
    __nv_bfloat16 h0, l0, h1, l1;
    bsplit(v0, h0, l0); bsplit(v1, h1, l1);
    uint32_t o = swz(row, lc >> 3) + ((lc << 1) & 15);
    sts32(sH + o, pk(h0, h1));
    sts32(sL + o, pk(l0, l1));
}

// ============================================================================
// fused fc1 -> fc2(+fc3 logit) -> att : one CTA per 128-row tile
// ============================================================================
__global__ __launch_bounds__(512, 1)
void fused_gemm(const float* __restrict__ F,
                const float* __restrict__ s1, const float* __restrict__ b1,
                const float* __restrict__ s2, const float* __restrict__ b2,
                const float* __restrict__ W3, const float* __restrict__ b3,
                const float* __restrict__ xyz,
                const float* __restrict__ pcen, const float* __restrict__ pnrm,
                const float* __restrict__ pmn,  const float* __restrict__ pmx,
                float* __restrict__ out)
{
    extern __shared__ __align__(16) char smx[];
    const uint32_t sb = (uint32_t)__cvta_generic_to_shared(smx);
    const uint32_t sAH = sb + OFF_AH, sAL = sb + OFF_AL;
    const uint32_t sBH = sb + OFF_BH, sBL = sb + OFF_BL;
    const uint32_t sCH = sb + OFF_CH, sCL = sb + OFF_CL;
    float* par = (float*)(smx + OFF_PAR);
    float *sc0 = par,       *bi0 = par + 128, *sc1 = par + 256, *bi1 = par + 384;
    float *ps2 = par + 512, *pb2 = par + 640, *pw3 = par + 768, *plg = par + 896;
    unsigned* pmax   = (unsigned*)(par + 1024);   // 128
    unsigned* prowm  = (unsigned*)(par + 1152);   // 128 row any-plane flags
    float4*   sn     = (float4*)(par + 1280);     // 64 planes: nx,ny,nz,off
    float4*   sbx    = (float4*)(par + 1536);     // 64 planes: minx,miny,maxx,maxy

    const int tid = threadIdx.x, wid = tid >> 5, t = tid & 31;
    const int rowBase = blockIdx.x * 128;
    const int warpM = (wid & 3) * 32, warpN = (wid >> 2) * 32;
    const int g = t >> 3;
    const int rA0 = warpM + (g & 1) * 8 + (t & 7), cgA = g >> 1;
    const int rB0 = warpN + (g >> 1) * 8 + (t & 7), cgB = g & 1;

    if (tid < 128) {
        sc0[tid] = s1[tid];        bi0[tid] = b1[tid];
        sc1[tid] = s1[128 + tid];  bi1[tid] = b1[128 + tid];
        ps2[tid] = s2[tid];        pb2[tid] = b2[tid];
        pw3[tid] = W3[tid];        plg[tid] = 0.f;  pmax[tid] = 0u;
    }
    if (tid < NPLANES) {
        float nx = pnrm[tid * 3], ny = pnrm[tid * 3 + 1], nz = pnrm[tid * 3 + 2];
        float off = nx * pcen[tid * 3] + ny * pcen[tid * 3 + 1] + nz * pcen[tid * 3 + 2];
        sn[tid]  = make_float4(nx, ny, nz, off);
        sbx[tid] = make_float4(pmn[tid * 3], pmn[tid * 3 + 1], pmx[tid * 3], pmx[tid * 3 + 1]);
    }

    // ---- stage W1 half0 -> B ; convert F -> A (hi/lo, swizzled)
    stage_w(sBH, sBL, g_W1h, g_W1l, 128, 0, 0, tid);
    {
        const float4 z4 = make_float4(0.f, 0.f, 0.f, 0.f);
        for (int i = tid; i < 4096; i += 512) {
            int r = i >> 5, c4 = i & 31;
            int gr = rowBase + r;
            float4 v = (gr < NPTS) ? *(const float4*)&F[(size_t)gr * CH + c4 * 4] : z4;
            __nv_bfloat16 h0, h1, h2v, h3, l0, l1, l2, l3;
            bsplit(v.x, h0, l0); bsplit(v.y, h1, l1);
            bsplit(v.z, h2v, l2); bsplit(v.w, h3, l3);
            uint32_t off = swz(r, c4 >> 1) + (c4 & 1) * 8;
            *(uint2*)(smx + OFF_AH + off) = make_uint2(pk(h0, h1), pk(h2v, h3));
            *(uint2*)(smx + OFF_AL + off) = make_uint2(pk(l0, l1), pk(l2, l3));
        }
    }
    cpa_wait();
    __syncthreads();

    // ---- per-row "any plane" mask (independent of GEMMs; gates gmem writes)
    if (tid < 128) {
        int gr = rowBase + tid;
        unsigned any = 0u;
        if (gr < NPTS) {
            float x = xyz[gr * 3], y = xyz[gr * 3 + 1], z = xyz[gr * 3 + 2];
            for (int p = 0; p < NPLANES; p++) {
                float4 nn = sn[p];
                float4 bb = sbx[p];
                bool ok = (fabsf(x * nn.x + y * nn.y + z * nn.z - nn.w) < 0.1f) &&
                          (x >= bb.x) && (x < bb.z) && (y >= bb.y) && (y < bb.w);
                any |= ok ? 1u : 0u;
            }
        }
        prowm[tid] = any;
    }

    float Cr[2][4][4];

    // ================= GEMM1 half 0: Hsm0 = relu((F@W1[:,0:128])*s+b) -> Cbuf
    ZERO_C(Cr);
    mma_phase(Cr, sAH, sAL, sBH, sBL, rA0, cgA, rB0, cgB);
    __syncthreads();                      // B free; A still holds F
    stage_w(sBH, sBL, g_W1h, g_W1l, 128, 128, 0, tid);   // W1 half1 (overlaps epi)
#pragma unroll
    for (int mi = 0; mi < 2; mi++) {
        int lr = warpM + mi * 16 + (t >> 2);
#pragma unroll
        for (int ni = 0; ni < 4; ni++) {
            int lc = warpN + ni * 8 + (t & 3) * 2;
            float s0v = sc0[lc], s1v = sc0[lc + 1], d0 = bi0[lc], d1 = bi0[lc + 1];
            st_split(sCH, sCL, lr,     lc, fmaxf(Cr[mi][ni][0] * s0v + d0, 0.f),
                                           fmaxf(Cr[mi][ni][1] * s1v + d1, 0.f));
            st_split(sCH, sCL, lr + 8, lc, fmaxf(Cr[mi][ni][2] * s0v + d0, 0.f),
                                           fmaxf(Cr[mi][ni][3] * s1v + d1, 0.f));
        }
    }
    cpa_wait();
    __syncthreads();

    // ================= GEMM1 half 1: Hsm1 -> Abuf (overwrites F)
    ZERO_C(Cr);
    mma_phase(Cr, sAH, sAL, sBH, sBL, rA0, cgA, rB0, cgB);
    __syncthreads();                      // A and B free
    stage_w(sBH, sBL, g_W2h, g_W2l, 256, 0, 0, tid);     // W2 k-chunk 0 (overlaps epi)
#pragma unroll
    for (int mi = 0; mi < 2; mi++) {
        int lr = warpM + mi * 16 + (t >> 2);
#pragma unroll
        for (int ni = 0; ni < 4; ni++) {
            int lc = warpN + ni * 8 + (t & 3) * 2;
            float s0v = sc1[lc], s1v = sc1[lc + 1], d0 = bi1[lc], d1 = bi1[lc + 1];
            st_split(sAH, sAL, lr,     lc, fmaxf(Cr[mi][ni][0] * s0v + d0, 0.f),
                                           fmaxf(Cr[mi][ni][1] * s1v + d1, 0.f));
            st_split(sAH, sAL, lr + 8, lc, fmaxf(Cr[mi][ni][2] * s0v + d0, 0.f),
                                           fmaxf(Cr[mi][ni][3] * s1v + d1, 0.f));
        }
    }
    cpa_wait();
    __syncthreads();

    // ================= GEMM2: h2 = relu((H@W2)*s2+b2), K=256 over C then A
    ZERO_C(Cr);
    mma_phase(Cr, sCH, sCL, sBH, sBL, rA0, cgA, rB0, cgB);    // k 0..127 (Hsm0)
    __syncthreads();                      // B free
    stage_w(sBH, sBL, g_W2h, g_W2l, 256, 0, 128, tid);   // W2 k-chunk 1
    cpa_wait();
    __syncthreads();
    mma_phase(Cr, sAH, sAL, sBH, sBL, rA0, cgA, rB0, cgB);    // k 128..255 (Hsm1)
    __syncthreads();                      // A, B, C free
    stage_w(sBH, sBL, g_Wah, g_Wal, 128, 0, 0, tid);     // Wa (overlaps epi)

    // epilogue fc2: h2 fp32 -> gmem (masked rows), split -> Cbuf, fused fc3 logit
#pragma unroll
    for (int mi = 0; mi < 2; mi++) {
        int lr = warpM + mi * 16 + (t >> 2);
        int gr0 = rowBase + lr, gr8 = gr0 + 8;
        bool w0 = (gr0 < NPTS) && prowm[lr];
        bool w8 = (gr8 < NPTS) && prowm[lr + 8];
        float lp0 = 0.f, lp8 = 0.f;
#pragma unroll
        for (int ni = 0; ni < 4; ni++) {
            int lc = warpN + ni * 8 + (t & 3) * 2;
            float s0v = ps2[lc], s1v = ps2[lc + 1], d0 = pb2[lc], d1 = pb2[lc + 1];
            float v0 = fmaxf(Cr[mi][ni][0] * s0v + d0, 0.f);
            float v1 = fmaxf(Cr[mi][ni][1] * s1v + d1, 0.f);
            float v2 = fmaxf(Cr[mi][ni][2] * s0v + d0, 0.f);
            float v3 = fmaxf(Cr[mi][ni][3] * s1v + d1, 0.f);
            lp0 += v0 * pw3[lc] + v1 * pw3[lc + 1];
            lp8 += v2 * pw3[lc] + v3 * pw3[lc + 1];
            st_split(sCH, sCL, lr,     lc, v0, v1);
            st_split(sCH, sCL, lr + 8, lc, v2, v3);
            if (w0) *(float2*)&g_h2[(size_t)gr0 * CH + lc] = make_float2(v0, v1);
            if (w8) *(float2*)&g_h2[(size_t)gr8 * CH + lc] = make_float2(v2, v3);
        }
        atomicAdd(&plg[lr], lp0);
        atomicAdd(&plg[lr + 8], lp8);
    }
    cpa_wait();
    __syncthreads();
    if (tid < 128 && rowBase + tid < NPTS) out[rowBase + tid] = plg[tid] + b3[0];

    // ================= GEMM3: a = h2 @ Wa (raw) + colmax (over ALL valid rows)
    ZERO_C(Cr);
    mma_phase(Cr, sCH, sCL, sBH, sBL, rA0, cgA, rB0, cgB);
#pragma unroll
    for (int mi = 0; mi < 2; mi++) {
        int lr = warpM + mi * 16 + (t >> 2);
        int gr0 = rowBase + lr, gr8 = gr0 + 8;
        bool w0 = (gr0 < NPTS) && prowm[lr];
        bool w8 = (gr8 < NPTS) && prowm[lr + 8];
#pragma unroll
        for (int ni = 0; ni < 4; ni++) {
            int lc = warpN + ni * 8 + (t & 3) * 2;
            float v0 = Cr[mi][ni][0], v1 = Cr[mi][ni][1];
            float v2 = Cr[mi][ni][2], v3 = Cr[mi][ni][3];
            if (w0) *(float2*)&g_a[(size_t)gr0 * CH + lc] = make_float2(v0, v1);
            if (w8) *(float2*)&g_a[(size_t)gr8 * CH + lc] = make_float2(v2, v3);
            unsigned e0 = 0u, e1 = 0u;
            if (gr0 < NPTS) { e0 = encf(v0); e1 = encf(v1); }
            if (gr8 < NPTS) {
                unsigned f2 = encf(v2), f3 = encf(v3);
                e0 = (f2 > e0) ? f2 : e0; e1 = (f3 > e1) ? f3 : e1;
            }
            if (e0) atomicMax(&pmax[lc], e0);
            if (e1) atomicMax(&pmax[lc + 1], e1);
        }
    }
    __syncthreads();
    if (tid < 128) atomicMax(&g_cmax[tid], pmax[tid]);
}

// ------------------------- sparse mask + attention accumulation --------------
__global__ void mask_accum(const float* __restrict__ xyz,
                           const float* __restrict__ center, const float* __restrict__ normal,
                           const float* __restrict__ pmin, const float* __restrict__ pmax,
                           const float* __restrict__ logit)
{
    __shared__ float4 sn[NPLANES];
    __shared__ float4 sbx[NPLANES];
    __shared__ float scm[CH];
    int tid = threadIdx.x;
    if (tid < NPLANES) {
        float nx = normal[tid * 3], ny = normal[tid * 3 + 1], nz = normal[tid * 3 + 2];
        float off = nx * center[tid * 3] + ny * center[tid * 3 + 1] + nz * center[tid * 3 + 2];
        sn[tid] = make_float4(nx, ny, nz, off);
        sbx[tid] = make_float4(pmin[tid * 3], pmin[tid * 3 + 1], pmax[tid * 3], pmax[tid * 3 + 1]);
    }
    if (tid < CH) scm[tid] = decf(g_cmax[tid]);
    __syncthreads();

    int n = blockIdx.x * blockDim.x + tid;
    unsigned long long m = 0ull;
    int sel = 0;
    if (n < NPTS) {
        float x = xyz[n * 3], y = xyz[n * 3 + 1], z = xyz[n * 3 + 2];
        sel = (logit[n] > 0.0f) ? 1 : 0;
        for (int p = 0; p < NPLANES; p++) {
            float4 nn = sn[p];
            float proj = x * nn.x + y * nn.y + z * nn.z;
            float4 bb = sbx[p];
            bool ok = (fabsf(proj - nn.w) < 0.1f) &&
                      (x >= bb.x) && (x < bb.z) && (y >= bb.y) && (y < bb.w);
            if (ok) m |= (1ull << p);
        }
    }

    int lane = tid & 31;
    for (;;) {
        unsigned act = __ballot_sync(0xffffffffu, m != 0ull);
        if (!act) break;
        int src = __ffs(act) - 1;
        unsigned long long ms = __shfl_sync(0xffffffffu, m, src);
        int ns  = __shfl_sync(0xffffffffu, n, src);
        int sls = __shfl_sync(0xffffffffu, sel, src);
        int p = __ffsll((long long)ms) - 1;
        if (lane == src) m &= (m - 1);

        float* num = g_num + ((sls ? 0 : 1) * NPLANES + p) * CH;
        float* den = g_den + ((sls ? 0 : 1) * NPLANES + p) * CH;
        const float* ar = g_a  + (size_t)ns * CH;
        const float* hr = g_h2 + (size_t)ns * CH;
#pragma unroll
        for (int i = 0; i < 4; i++) {
            int c = lane + 32 * i;
            float e = expf(ar[c] - scm[c]);
            atomicAdd(&num[c], e * hr[c]);
            atomicAdd(&den[c], e);
        }
    }
}

// ------------------------- finalize ------------------------------------------
__global__ void finalize_kernel(const float* __restrict__ Wm, const float* __restrict__ bm,
                                const float* __restrict__ center, const float* __restrict__ normal,
                                const float* __restrict__ pmin, const float* __restrict__ pmax,
                                float* __restrict__ out)
{
    int bp = blockIdx.x;
    int pool = bp >> 6, p = bp & 63;
    __shared__ float agg[CH];
    int j = threadIdx.x;
    int base = (pool * NPLANES + p) * CH;
    agg[j] = g_num[base + j] / (g_den[base + j] + 1e-9f);
    __syncthreads();

    float s = __ldg(&bm[j]);
#pragma unroll
    for (int c = 0; c < CH; c++) s += agg[c] * __ldg(&Wm[c * CH + j]);
    s = fmaxf(s, 0.f);

    float* ob = out + NPTS + (size_t)pool * NPLANES * FEAT_OUT + p * FEAT_OUT;
    ob[j] = s;
    if (j < 12) {
        float v;
        if (j < 3)      v = center[p * 3 + j];
        else if (j < 6) v = normal[p * 3 + (j - 3)];
        else if (j < 9) v = pmin[p * 3 + (j - 6)];
        else            v = pmax[p * 3 + (j - 9)];
        ob[CH + j] = v;
    }
}

// ------------------------- launch --------------------------------------------
extern "C" void kernel_launch(void* const* d_in, const int* in_sizes, int n_in,
                              void* d_out, int out_size)
{
    const float* feature = (const float*)d_in[0];
    const float* xyz     = (const float*)d_in[1];
    const float* center  = (const float*)d_in[2];
    const float* normal  = (const float*)d_in[3];
    const float* pmin    = (const float*)d_in[4];
    const float* pmax    = (const float*)d_in[5];
    const float* W1      = (const float*)d_in[6];
    const float* s1      = (const float*)d_in[7];
    const float* b1      = (const float*)d_in[8];
    const float* W2      = (const float*)d_in[9];
    const float* s2      = (const float*)d_in[10];
    const float* b2      = (const float*)d_in[11];
    const float* W3      = (const float*)d_in[12];
    const float* b3      = (const float*)d_in[13];
    const float* Wa      = (const float*)d_in[14];
    const float* Wm      = (const float*)d_in[15];
    const float* bm      = (const float*)d_in[16];
    float* out = (float*)d_out;

    cudaFuncSetAttribute(fused_gemm, cudaFuncAttributeMaxDynamicSharedMemorySize, SMEM_TOT);

    const int MB = (NPTS + 127) / 128;   // 782

    prep_kernel<<<320, 256>>>(W1, W2, Wa);
    fused_gemm<<<MB, 512, SMEM_TOT>>>(feature, s1, b1, s2, b2, W3, b3,
                                      xyz, center, normal, pmin, pmax, out);
    mask_accum<<<(NPTS + 255) / 256, 256>>>(xyz, center, normal, pmin, pmax, out);
    finalize_kernel<<<128, 128>>>(Wm, bm, center, normal, pmin, pmax, out);
}